// round 8
// baseline (speedup 1.0000x reference)
#include <cuda_runtime.h>
#include <cuda_bf16.h>
#include <cstdint>

#define NCTA 128
#define NTHR 256
static constexpr int Bn = 32, Tn = 64, Sn = 128, Hn = 512, En = 512, Vn = 32000;
static constexpr float NEGV = -1e4f;

// ---------------- device scratch (allocation-free) ----------------
__device__ __align__(16) float g_xT[Tn][En][Bn];
__device__ __align__(16) float g_feedT[Hn][Bn];
__device__ __align__(16) float g_h0T[2][Hn][Bn];
__device__ __align__(16) float g_h1T[2][Hn][Bn];
__device__ __align__(16) float g_qT[Hn][Bn];
__device__ __align__(16) float g_ctxT[Hn][Bn];
__device__ __align__(16) float g_dec[Bn * Tn][Hn];
__device__ __nv_bfloat16 g_Ahi[Bn * Tn * En];
__device__ __nv_bfloat16 g_Alo[Bn * Tn * En];
__device__ __nv_bfloat16 g_Bhi[Vn * En];
__device__ __nv_bfloat16 g_Blo[Vn * En];
__device__ unsigned g_count;
__device__ volatile unsigned g_gen;

// ---------------- small helpers ----------------
__device__ __forceinline__ uint32_t s2u(const void* p)
{
    uint32_t a;
    asm("{ .reg .u64 t; cvta.to.shared.u64 t, %1; cvt.u32.u64 %0, t; }" : "=r"(a) : "l"(p));
    return a;
}
__device__ __forceinline__ void cp16(uint32_t s, const void* g)
{
    asm volatile("cp.async.cg.shared.global [%0], [%1], 16;" :: "r"(s), "l"(g) : "memory");
}
__device__ __forceinline__ float sigm(float x) { return 1.f / (1.f + __expf(-x)); }

__device__ __forceinline__ unsigned long long pack2(float x)
{ unsigned long long r; asm("mov.b64 %0, {%1, %1};" : "=l"(r) : "f"(x)); return r; }
__device__ __forceinline__ void ffma2(unsigned long long& d, unsigned long long a, unsigned long long b)
{ asm("fma.rn.f32x2 %0, %1, %2, %0;" : "+l"(d) : "l"(a), "l"(b)); }
__device__ __forceinline__ float2 unpack2(unsigned long long v)
{ float2 r; asm("mov.b64 {%0, %1}, %2;" : "=f"(r.x), "=f"(r.y) : "l"(v)); return r; }

// smem matvec segment: weights (smem) x act chunk (smem, [k][32] layout)
template<int KLEN>
__device__ __forceinline__ void mvseg_s(const float* __restrict__ w,
                                        const float* __restrict__ act, int q,
                                        unsigned long long& A0, unsigned long long& A1)
{
    const char* ap = (const char*)act + q * 16;
#pragma unroll
    for (int k0 = 0; k0 < KLEN; k0 += 8) {
        float4 w0 = *(const float4*)(w + k0);
        float4 w1 = *(const float4*)(w + k0 + 4);
        ulonglong2 av[8];
#pragma unroll
        for (int kk = 0; kk < 8; kk++)
            av[kk] = *(const ulonglong2*)(ap + (k0 + kk) * 128);
        float ws[8] = {w0.x, w0.y, w0.z, w0.w, w1.x, w1.y, w1.z, w1.w};
#pragma unroll
        for (int kk = 0; kk < 8; kk++) {
            unsigned long long wp = pack2(ws[kk]);
            ffma2(A0, wp, av[kk].x);
            ffma2(A1, wp, av[kk].y);
        }
    }
}

// ---------------- grid barrier (all 128 CTAs co-resident) ----------------
__device__ __forceinline__ void gbar()
{
    __threadfence();
    __syncthreads();
    if (threadIdx.x == 0) {
        unsigned g = g_gen;
        unsigned a = atomicAdd(&g_count, 1u);
        if (a == NCTA - 1u) {
            g_count = 0u;
            __threadfence();
            g_gen = g + 1u;
        } else {
            while (g_gen == g) { }
        }
    }
    __syncthreads();
    __threadfence();
}

// smem layout (dynamic): padded strides kill LDS bank conflicts
static constexpr int WA_STR = 1540, WB_STR = 1028, WC_STR = 516, WE_STR = 1028;
static constexpr int OFF_WA = 0;
static constexpr int OFF_WB = OFF_WA + 16 * WA_STR * 4;          // 98560
static constexpr int OFF_WC = OFF_WB + 16 * WB_STR * 4;          // 164352
static constexpr int OFF_WE = OFF_WC + 4 * WC_STR * 4;           // 172608
static constexpr int OFF_ACT = OFF_WE + 4 * WE_STR * 4;          // 189056
static constexpr int DSMEM = OFF_ACT + 2 * 16384;                // 221824

// ---------------- persistent recurrence ----------------
__global__ void __launch_bounds__(NTHR, 1)
recurrent_kernel(const int* __restrict__ tokens, const float* __restrict__ enc,
                 const int* __restrict__ mask, const float* __restrict__ embed,
                 const float* __restrict__ w_ih0, const float* __restrict__ w_hh0,
                 const float* __restrict__ b_ih0, const float* __restrict__ b_hh0,
                 const float* __restrict__ w_ih1, const float* __restrict__ w_hh1,
                 const float* __restrict__ b_ih1, const float* __restrict__ b_hh1,
                 const float* __restrict__ attn_in_w, const float* __restrict__ attn_out_w)
{
    extern __shared__ __align__(16) char dsm[];
    float* wA = (float*)(dsm + OFF_WA);
    float* wB = (float*)(dsm + OFF_WB);
    float* wC = (float*)(dsm + OFF_WC);
    float* wE = (float*)(dsm + OFF_WE);
    char*  abuf = dsm + OFF_ACT;
    const uint32_t su_act = s2u(abuf);

    const int tid = threadIdx.x, cta = blockIdx.x;
    const int warp = tid >> 5, lane = tid & 31;
    const int gtid = cta * NTHR + tid;

    __shared__ __align__(16) float sA[2][4][4][32];   // [kh][g][r][batch]
    __shared__ __align__(16) float s_q[512];
    __shared__ float s_sc[128];
    __shared__ float s_red[32];

    // ---- init recurrent state ----
    for (int i = gtid; i < Hn * Bn; i += NCTA * NTHR) {
        (&g_feedT[0][0])[i] = 0.f;
        (&g_h0T[0][0][0])[i] = 0.f; (&g_h0T[1][0][0])[i] = 0.f;
        (&g_h1T[0][0][0])[i] = 0.f; (&g_h1T[1][0][0])[i] = 0.f;
    }
    // ---- embed gather+transpose ----
    {
        int gw = gtid >> 5;
#pragma unroll
        for (int rep = 0; rep < 2; rep++) {
            int p = gw * 2 + rep;
            int b = p & 31, t0 = p >> 5;
            int tok = __ldg(tokens + b * Tn + t0);
            const float4* er = (const float4*)(embed + (size_t)tok * En);
#pragma unroll
            for (int i = 0; i < 4; i++) {
                float4 v = __ldg(er + i * 32 + lane);
                int e = (i * 32 + lane) * 4;
                g_xT[t0][e][b] = v.x; g_xT[t0][e + 1][b] = v.y;
                g_xT[t0][e + 2][b] = v.z; g_xT[t0][e + 3][b] = v.w;
            }
        }
    }

    // ---- stage this CTA's weight slice into smem (once) ----
    for (int rho = 0; rho < 16; rho++) {
        int gg = rho >> 2, gate = rho & 3;
        int grow = gate * 512 + cta * 4 + gg;
        ((float4*)(wA + rho * WA_STR))[tid] =
            __ldg((const float4*)(w_ih0 + (size_t)grow * 1024) + tid);
        if (tid < 128) {
            ((float4*)(wA + rho * WA_STR + 1024))[tid] =
                __ldg((const float4*)(w_hh0 + (size_t)grow * 512) + tid);
            ((float4*)(wB + rho * WB_STR))[tid] =
                __ldg((const float4*)(w_ih1 + (size_t)grow * 512) + tid);
            ((float4*)(wB + rho * WB_STR + 512))[tid] =
                __ldg((const float4*)(w_hh1 + (size_t)grow * 512) + tid);
        }
    }
    for (int rr = 0; rr < 4; rr++) {
        if (tid < 128)
            ((float4*)(wC + rr * WC_STR))[tid] =
                __ldg((const float4*)(attn_in_w + (size_t)(cta * 4 + rr) * 512) + tid);
        ((float4*)(wE + rr * WE_STR))[tid] =
            __ldg((const float4*)(attn_out_w + (size_t)(cta * 4 + rr) * 1024) + tid);
    }
    gbar();

    const int g = warp >> 1, kh = warp & 1;
    const int r = lane >> 3, q = lane & 7;
    const int rho = g * 4 + r;

    float c0r = 0.f, c1r = 0.f;
    float biA[4], biB[4];
    if (tid < 128) {
        int jj = tid >> 5, ju = cta * 4 + jj;
#pragma unroll
        for (int rr = 0; rr < 4; rr++) {
            biA[rr] = __ldg(b_ih0 + ju + 512 * rr) + __ldg(b_hh0 + ju + 512 * rr);
            biB[rr] = __ldg(b_ih1 + ju + 512 * rr) + __ldg(b_hh1 + ju + 512 * rr);
        }
    }

    // 16KB chunk stage via cp.async (4 x 16B per thread)
    auto stage = [&](int slot, const float* src) {
        uint32_t d = su_act + slot * 16384 + tid * 16;
        const float* s = src + tid * 4;
        cp16(d, s); cp16(d + 4096, s + 1024);
        cp16(d + 8192, s + 2048); cp16(d + 12288, s + 3072);
        asm volatile("cp.async.commit_group;" ::: "memory");
    };
    auto run_pipe = [&](int NC, auto srcf, auto body) {
        stage(0, srcf(0));
        for (int c = 0; c < NC; c++) {
            if (c + 1 < NC) {
                stage((c + 1) & 1, srcf(c + 1));
                asm volatile("cp.async.wait_group 1;" ::: "memory");
            } else {
                asm volatile("cp.async.wait_group 0;" ::: "memory");
            }
            __syncthreads();
            body(c, (const float*)(abuf + (c & 1) * 16384));
            __syncthreads();
        }
    };

    for (int t = 0; t < Tn; t++) {
        const int cur = t & 1, prv = cur ^ 1;

        // ---------- Phase A: LSTM layer 0 gates (concat K = x512|feed512|h0 512) ----------
        {
            unsigned long long A0 = 0ull, A1 = 0ull;
            const float* wAp = wA + rho * WA_STR;
            run_pipe(12,
                [&](int c) -> const float* {
                    if (c < 4) return &g_xT[t][c * 128][0];
                    if (c < 8) return &g_feedT[(c - 4) * 128][0];
                    return &g_h0T[prv][(c - 8) * 128][0];
                },
                [&](int c, const float* bufc) {
                    mvseg_s<64>(wAp + c * 128 + kh * 64, bufc + kh * 64 * 32, q, A0, A1);
                });
            float2 v0 = unpack2(A0), v1 = unpack2(A1);
            *(float4*)&sA[kh][g][r][q * 4] = make_float4(v0.x, v0.y, v1.x, v1.y);
            __syncthreads();
            if (tid < 128) {
                int b = tid & 31, jj = tid >> 5;
                float gi = sA[0][jj][0][b] + sA[1][jj][0][b] + biA[0];
                float gf = sA[0][jj][1][b] + sA[1][jj][1][b] + biA[1];
                float gg = sA[0][jj][2][b] + sA[1][jj][2][b] + biA[2];
                float go = sA[0][jj][3][b] + sA[1][jj][3][b] + biA[3];
                c0r = sigm(gf) * c0r + sigm(gi) * tanhf(gg);
                g_h0T[cur][cta * 4 + jj][b] = sigm(go) * tanhf(c0r);
            }
        }
        gbar();

        // ---------- Phase B: LSTM layer 1 gates (K = h0cur 512 | h1prv 512) ----------
        {
            unsigned long long A0 = 0ull, A1 = 0ull;
            const float* wBp = wB + rho * WB_STR;
            run_pipe(8,
                [&](int c) -> const float* {
                    if (c < 4) return &g_h0T[cur][c * 128][0];
                    return &g_h1T[prv][(c - 4) * 128][0];
                },
                [&](int c, const float* bufc) {
                    mvseg_s<64>(wBp + c * 128 + kh * 64, bufc + kh * 64 * 32, q, A0, A1);
                });
            float2 v0 = unpack2(A0), v1 = unpack2(A1);
            *(float4*)&sA[kh][g][r][q * 4] = make_float4(v0.x, v0.y, v1.x, v1.y);
            __syncthreads();
            if (tid < 128) {
                int b = tid & 31, jj = tid >> 5;
                float gi = sA[0][jj][0][b] + sA[1][jj][0][b] + biB[0];
                float gf = sA[0][jj][1][b] + sA[1][jj][1][b] + biB[1];
                float gg = sA[0][jj][2][b] + sA[1][jj][2][b] + biB[2];
                float go = sA[0][jj][3][b] + sA[1][jj][3][b] + biB[3];
                c1r = sigm(gf) * c1r + sigm(gi) * tanhf(gg);
                g_h1T[cur][cta * 4 + jj][b] = sigm(go) * tanhf(c1r);
            }
        }
        gbar();

        // ---------- Phase C: q = attn_in_w @ h1 (4 rows, K=512) ----------
        {
            unsigned long long A0 = 0ull, A1 = 0ull;
            const int seg = kh * 2 + (r >> 1);   // which chunk this lane owns
            const int klocal = (r & 1) * 64;
            const float* wCp = wC + g * WC_STR;
            run_pipe(4,
                [&](int c) -> const float* { return &g_h1T[cur][c * 128][0]; },
                [&](int c, const float* bufc) {
                    if (seg == c)
                        mvseg_s<64>(wCp + c * 128 + klocal, bufc + klocal * 32, q, A0, A1);
                });
            float2 v0 = unpack2(A0), v1 = unpack2(A1);
            *(float4*)&sA[kh][g][r][q * 4] = make_float4(v0.x, v0.y, v1.x, v1.y);
            __syncthreads();
            if (tid < 128) {
                int b = tid & 31, jj = tid >> 5;
                float s = 0.f;
#pragma unroll
                for (int rr = 0; rr < 4; rr++) s += sA[0][jj][rr][b] + sA[1][jj][rr][b];
                g_qT[cta * 4 + jj][b] = s;
            }
        }
        gbar();

        // ---------- Phase D: scores -> softmax -> ctx (one CTA per batch) ----------
        if (cta < Bn) {
            const int b = cta;
            for (int k = tid; k < 512; k += NTHR) s_q[k] = __ldca(&g_qT[k][b]);
            __syncthreads();
            for (int i = 0; i < 16; i++) {
                int sp = warp * 16 + i;
                const float4* er = (const float4*)(enc + ((size_t)b * Sn + sp) * Hn);
                const float4* qr = (const float4*)s_q;
                float acc = 0.f;
#pragma unroll
                for (int c4 = 0; c4 < 4; c4++) {
                    float4 e = __ldg(er + c4 * 32 + lane);
                    float4 q4 = qr[c4 * 32 + lane];
                    acc += e.x * q4.x + e.y * q4.y + e.z * q4.z + e.w * q4.w;
                }
#pragma unroll
                for (int o = 16; o; o >>= 1) acc += __shfl_xor_sync(~0u, acc, o);
                if (lane == 0)
                    s_sc[sp] = (__ldg(mask + b * Sn + sp) == 0) ? NEGV : acc;
            }
            __syncthreads();
            float mv = (tid < 128) ? s_sc[tid] : -3e38f;
#pragma unroll
            for (int o = 16; o; o >>= 1) mv = fmaxf(mv, __shfl_xor_sync(~0u, mv, o));
            if (lane == 0) s_red[warp] = mv;
            __syncthreads();
            if (tid == 0) {
                float m = s_red[0];
                for (int w = 1; w < 8; w++) m = fmaxf(m, s_red[w]);
                s_red[16] = m;
            }
            __syncthreads();
            float ev = 0.f;
            if (tid < 128) ev = __expf(s_sc[tid] - s_red[16]);
            float sv = ev;
#pragma unroll
            for (int o = 16; o; o >>= 1) sv += __shfl_xor_sync(~0u, sv, o);
            if (lane == 0) s_red[warp] = sv;
            __syncthreads();
            if (tid == 0) {
                float s = 0.f;
                for (int w = 0; w < 8; w++) s += s_red[w];
                s_red[17] = 1.f / s;
            }
            __syncthreads();
            if (tid < 128) s_sc[tid] = ev * s_red[17];
            __syncthreads();
#pragma unroll
            for (int rep = 0; rep < 2; rep++) {
                int h = tid + rep * 256;
                const float* ep = enc + (size_t)b * Sn * Hn + h;
                float acc = 0.f;
#pragma unroll 16
                for (int s = 0; s < Sn; s++) acc += s_sc[s] * __ldg(ep + s * Hn);
                g_ctxT[h][b] = acc;
            }
        }
        gbar();

        // ---------- Phase E: input_feed = tanh(attn_out_w @ [ctx512; h1cur512]) ----------
        {
            unsigned long long A0 = 0ull, A1 = 0ull;
            const int seg = kh * 4 + r;
            const float* wEp = wE + g * WE_STR;
            run_pipe(8,
                [&](int c) -> const float* {
                    if (c < 4) return &g_ctxT[c * 128][0];
                    return &g_h1T[cur][(c - 4) * 128][0];
                },
                [&](int c, const float* bufc) {
                    if (seg == c)
                        mvseg_s<128>(wEp + c * 128, bufc, q, A0, A1);
                });
            float2 v0 = unpack2(A0), v1 = unpack2(A1);
            *(float4*)&sA[kh][g][r][q * 4] = make_float4(v0.x, v0.y, v1.x, v1.y);
            __syncthreads();
            if (tid < 128) {
                int b = tid & 31, jj = tid >> 5;
                float s = 0.f;
#pragma unroll
                for (int rr = 0; rr < 4; rr++) s += sA[0][jj][rr][b] + sA[1][jj][rr][b];
                float f = tanhf(s);
                g_feedT[cta * 4 + jj][b] = f;
                g_dec[b * Tn + t][cta * 4 + jj] = f;
            }
        }
        gbar();
    }
}

// ---------------- SIMT f32x2 gemm (out_proj) -> bf16 hi/lo directly ----------------
__device__ __forceinline__ void split_bf16(float v, __nv_bfloat16& h, __nv_bfloat16& l)
{
    h = __float2bfloat16(v);
    l = __float2bfloat16(v - __bfloat162float(h));
}

__global__ void __launch_bounds__(256)
gemm_nt_split(const float* __restrict__ A, const float* __restrict__ W,
              const float* __restrict__ bias,
              __nv_bfloat16* __restrict__ Chi, __nv_bfloat16* __restrict__ Clo,
              int M, int N, int K)
{
    __shared__ __align__(16) float As[16][128];
    __shared__ __align__(16) float Ws[16][128];
    const int m0 = blockIdx.y * 128, n0 = blockIdx.x * 128;
    const int tid = threadIdx.x;
    const int tx = tid & 15, ty = tid >> 4;
    const int lrow = tid >> 1, lcol = (tid & 1) * 8;

    unsigned long long acc2[8][4];
#pragma unroll
    for (int i = 0; i < 8; i++)
#pragma unroll
        for (int jj = 0; jj < 4; jj++) acc2[i][jj] = 0ull;

    const float* Aload = A + (size_t)(m0 + lrow) * K + lcol;
    const float* Wload = W + (size_t)(n0 + lrow) * K + lcol;

    for (int k0 = 0; k0 < K; k0 += 16) {
        float4 a0 = __ldg((const float4*)(Aload + k0));
        float4 a1 = __ldg((const float4*)(Aload + k0 + 4));
        float4 w0 = __ldg((const float4*)(Wload + k0));
        float4 w1 = __ldg((const float4*)(Wload + k0 + 4));
        __syncthreads();
        As[lcol + 0][lrow] = a0.x; As[lcol + 1][lrow] = a0.y;
        As[lcol + 2][lrow] = a0.z; As[lcol + 3][lrow] = a0.w;
        As[lcol + 4][lrow] = a1.x; As[lcol + 5][lrow] = a1.y;
        As[lcol + 6][lrow] = a1.z; As[lcol + 7][lrow] = a1.w;
        Ws[lcol + 0][lrow] = w0.x; Ws[lcol + 1][lrow] = w0.y;
        Ws[lcol + 2][lrow] = w0.z; Ws[lcol + 3][lrow] = w0.w;
        Ws[lcol + 4][lrow] = w1.x; Ws[lcol + 5][lrow] = w1.y;
        Ws[lcol + 6][lrow] = w1.z; Ws[lcol + 7][lrow] = w1.w;
        __syncthreads();
#pragma unroll
        for (int kk = 0; kk < 16; kk++) {
            float4 av0 = *(const float4*)&As[kk][ty * 8];
            float4 av1 = *(const float4*)&As[kk][ty * 8 + 4];
            const ulonglong2* wp = (const ulonglong2*)&Ws[kk][tx * 8];
            ulonglong2 b01 = wp[0], b23 = wp[1];
            float a8[8] = {av0.x, av0.y, av0.z, av0.w, av1.x, av1.y, av1.z, av1.w};
#pragma unroll
            for (int i = 0; i < 8; i++) {
                unsigned long long a2 = pack2(a8[i]);
                ffma2(acc2[i][0], a2, b01.x);
                ffma2(acc2[i][1], a2, b01.y);
                ffma2(acc2[i][2], a2, b23.x);
                ffma2(acc2[i][3], a2, b23.y);
            }
        }
    }
#pragma unroll
    for (int i = 0; i < 8; i++) {
        size_t rowoff = (size_t)(m0 + ty * 8 + i) * N + n0 + tx * 8;
        unsigned short tmph[8], tmpl[8];
#pragma unroll
        for (int jj = 0; jj < 4; jj++) {
            float2 v = unpack2(acc2[i][jj]);
            v.x += __ldg(bias + n0 + tx * 8 + 2 * jj);
            v.y += __ldg(bias + n0 + tx * 8 + 2 * jj + 1);
            __nv_bfloat16 h0, l0, h1, l1;
            split_bf16(v.x, h0, l0);
            split_bf16(v.y, h1, l1);
            tmph[2 * jj] = __bfloat16_as_ushort(h0); tmph[2 * jj + 1] = __bfloat16_as_ushort(h1);
            tmpl[2 * jj] = __bfloat16_as_ushort(l0); tmpl[2 * jj + 1] = __bfloat16_as_ushort(l1);
        }
        uint2 H, L, H2, L2;
        H.x = (uint32_t)tmph[0] | ((uint32_t)tmph[1] << 16);
        H.y = (uint32_t)tmph[2] | ((uint32_t)tmph[3] << 16);
        L.x = (uint32_t)tmpl[0] | ((uint32_t)tmpl[1] << 16);
        L.y = (uint32_t)tmpl[2] | ((uint32_t)tmpl[3] << 16);
        H2.x = (uint32_t)tmph[4] | ((uint32_t)tmph[5] << 16);
        H2.y = (uint32_t)tmph[6] | ((uint32_t)tmph[7] << 16);
        L2.x = (uint32_t)tmpl[4] | ((uint32_t)tmpl[5] << 16);
        L2.y = (uint32_t)tmpl[6] | ((uint32_t)tmpl[7] << 16);
        *(uint2*)(Chi + rowoff) = H;  *(uint2*)(Chi + rowoff + 4) = H2;
        *(uint2*)(Clo + rowoff) = L;  *(uint2*)(Clo + rowoff + 4) = L2;
    }
}

// ---------------- fp32 -> bf16 hi/lo split (for embed) ----------------
__global__ void __launch_bounds__(256)
conv_split(const float4* __restrict__ src, uint2* __restrict__ hi, uint2* __restrict__ lo)
{
    int i = blockIdx.x * 256 + threadIdx.x;
    float4 v = __ldg(src + i);
    __nv_bfloat16 h0, l0, h1, l1, h2, l2, h3, l3;
    split_bf16(v.x, h0, l0); split_bf16(v.y, h1, l1);
    split_bf16(v.z, h2, l2); split_bf16(v.w, h3, l3);
    uint2 H, L;
    H.x = (uint32_t)__bfloat16_as_ushort(h0) | ((uint32_t)__bfloat16_as_ushort(h1) << 16);
    H.y = (uint32_t)__bfloat16_as_ushort(h2) | ((uint32_t)__bfloat16_as_ushort(h3) << 16);
    L.x = (uint32_t)__bfloat16_as_ushort(l0) | ((uint32_t)__bfloat16_as_ushort(l1) << 16);
    L.y = (uint32_t)__bfloat16_as_ushort(l2) | ((uint32_t)__bfloat16_as_ushort(l3) << 16);
    hi[i] = H; lo[i] = L;
}

// ---------------- mma.sync bf16 3-pass GEMM: C = A @ B^T ----------------
static constexpr int KC = 32;
static constexpr int NCHUNK = En / KC;
static constexpr int ROWB = 80;
static constexpr int MATB = 128 * ROWB;
static constexpr int STAGEB = 4 * MATB;
static constexpr int GSMEM2 = 2 * STAGEB;

__device__ __forceinline__ void ldmA(uint32_t* r, uint32_t addr)
{
    asm volatile("ldmatrix.sync.aligned.m8n8.x4.shared.b16 {%0,%1,%2,%3}, [%4];"
                 : "=r"(r[0]), "=r"(r[1]), "=r"(r[2]), "=r"(r[3]) : "r"(addr));
}
__device__ __forceinline__ void ldmB(uint32_t* r, uint32_t addr)
{
    asm volatile("ldmatrix.sync.aligned.m8n8.x2.shared.b16 {%0,%1}, [%2];"
                 : "=r"(r[0]), "=r"(r[1]) : "r"(addr));
}
__device__ __forceinline__ void mma16816(float* d, const uint32_t* a, const uint32_t* b)
{
    asm volatile("mma.sync.aligned.m16n8k16.row.col.f32.bf16.bf16.f32 "
                 "{%0,%1,%2,%3}, {%4,%5,%6,%7}, {%8,%9}, {%0,%1,%2,%3};"
                 : "+f"(d[0]), "+f"(d[1]), "+f"(d[2]), "+f"(d[3])
                 : "r"(a[0]), "r"(a[1]), "r"(a[2]), "r"(a[3]), "r"(b[0]), "r"(b[1]));
}

__global__ void __launch_bounds__(256, 1)
gemm_bf16(const __nv_bfloat16* __restrict__ Ahi, const __nv_bfloat16* __restrict__ Alo,
          const __nv_bfloat16* __restrict__ Bhi, const __nv_bfloat16* __restrict__ Blo,
          float* __restrict__ C, int N, int K)
{
    extern __shared__ char smem[];
    const uint32_t su = s2u(smem);
    const int tid = threadIdx.x, wid = tid >> 5, lane = tid & 31;
    const int m0 = blockIdx.x * 128, n0 = blockIdx.y * 128;
    const int wm = wid & 1, wn = wid >> 1;

    const int ci0 = tid;
    auto load_stage = [&](int chunk) {
        const uint32_t sb = su + (chunk & 1) * STAGEB;
#pragma unroll
        for (int r8 = 0; r8 < 8; r8++) {
            int ci = ci0 + r8 * 256;
            int mat = ci >> 9, rem = ci & 511;
            int row = rem >> 2, seg = rem & 3;
            const __nv_bfloat16* g;
            if (mat == 0)      g = Ahi + (size_t)(m0 + row) * K + chunk * KC + seg * 8;
            else if (mat == 1) g = Alo + (size_t)(m0 + row) * K + chunk * KC + seg * 8;
            else if (mat == 2) g = Bhi + (size_t)(n0 + row) * K + chunk * KC + seg * 8;
            else               g = Blo + (size_t)(n0 + row) * K + chunk * KC + seg * 8;
            cp16(sb + mat * MATB + row * ROWB + seg * 16, g);
        }
        asm volatile("cp.async.commit_group;" ::: "memory");
    };

    float acc[4][4][4];
#pragma unroll
    for (int i = 0; i < 4; i++)
#pragma unroll
        for (int jj = 0; jj < 4; jj++)
#pragma unroll
            for (int k = 0; k < 4; k++) acc[i][jj][k] = 0.f;

    load_stage(0);
    load_stage(1);

    for (int c = 0; c < NCHUNK; c++) {
        if (c < NCHUNK - 1) asm volatile("cp.async.wait_group 1;" ::: "memory");
        else                asm volatile("cp.async.wait_group 0;" ::: "memory");
        __syncthreads();
        const uint32_t sb = su + (c & 1) * STAGEB;
        const uint32_t aHiB = sb,            aLoB = sb + MATB;
        const uint32_t bHiB = sb + 2 * MATB, bLoB = sb + 3 * MATB;
#pragma unroll
        for (int ks = 0; ks < 2; ks++) {
            const uint32_t aoff = (uint32_t)((wm * 64 + (lane & 15)) * ROWB
                                             + (ks * 16 + (lane >> 4) * 8) * 2);
            const int l = lane & 15;
            const uint32_t boff = (uint32_t)((wn * 32 + (l & 7)) * ROWB
                                             + (ks * 16 + (l >> 3) * 8) * 2);
            uint32_t ah[4][4], al[4][4], bh[4][2], bl[4][2];
#pragma unroll
            for (int mi = 0; mi < 4; mi++) {
                ldmA(ah[mi], aHiB + aoff + mi * 16 * ROWB);
                ldmA(al[mi], aLoB + aoff + mi * 16 * ROWB);
            }
#pragma unroll
            for (int ni = 0; ni < 4; ni++) {
                ldmB(bh[ni], bHiB + boff + ni * 8 * ROWB);
                ldmB(bl[ni], bLoB + boff + ni * 8 * ROWB);
            }
#pragma unroll
            for (int mi = 0; mi < 4; mi++)
#pragma unroll
                for (int ni = 0; ni < 4; ni++) {
                    mma16816(acc[mi][ni], ah[mi], bh[ni]);
                    mma16816(acc[mi][ni], ah[mi], bl[ni]);
                    mma16816(acc[mi][ni], al[mi], bh[ni]);
                }
        }
        __syncthreads();
        if (c + 2 < NCHUNK) load_stage(c + 2);
    }

    const int mbase = m0 + wm * 64 + (lane >> 2);
    const int nbase = n0 + wn * 32 + (lane & 3) * 2;
#pragma unroll
    for (int mi = 0; mi < 4; mi++)
#pragma unroll
        for (int ni = 0; ni < 4; ni++) {
            float* p0 = C + (size_t)(mbase + mi * 16) * N + nbase + ni * 8;
            float* p1 = C + (size_t)(mbase + mi * 16 + 8) * N + nbase + ni * 8;
            *(float2*)p0 = make_float2(acc[mi][ni][0], acc[mi][ni][1]);
            *(float2*)p1 = make_float2(acc[mi][ni][2], acc[mi][ni][3]);
        }
}

extern "C" void kernel_launch(void* const* d_in, const int* in_sizes, int n_in,
                              void* d_out, int out_size)
{
    const int*   tokens     = (const int*)d_in[0];
    const float* enc        = (const float*)d_in[1];
    const int*   mask       = (const int*)d_in[2];
    const float* embed      = (const float*)d_in[3];
    const float* w_ih0      = (const float*)d_in[4];
    const float* w_hh0      = (const float*)d_in[5];
    const float* b_ih0      = (const float*)d_in[6];
    const float* b_hh0      = (const float*)d_in[7];
    const float* w_ih1      = (const float*)d_in[8];
    const float* w_hh1      = (const float*)d_in[9];
    const float* b_ih1      = (const float*)d_in[10];
    const float* b_hh1      = (const float*)d_in[11];
    const float* attn_in_w  = (const float*)d_in[12];
    const float* attn_out_w = (const float*)d_in[13];
    const float* out_proj_w = (const float*)d_in[14];
    const float* out_proj_b = (const float*)d_in[15];
    float* out = (float*)d_out;

    float *dec;
    __nv_bfloat16 *Ahi, *Alo, *Bhi, *Blo;
    cudaGetSymbolAddress((void**)&dec, g_dec);
    cudaGetSymbolAddress((void**)&Ahi, g_Ahi);
    cudaGetSymbolAddress((void**)&Alo, g_Alo);
    cudaGetSymbolAddress((void**)&Bhi, g_Bhi);
    cudaGetSymbolAddress((void**)&Blo, g_Blo);

    cudaFuncSetAttribute(gemm_bf16, cudaFuncAttributeMaxDynamicSharedMemorySize, GSMEM2);
    cudaFuncSetAttribute(recurrent_kernel, cudaFuncAttributeMaxDynamicSharedMemorySize, DSMEM);

    static cudaStream_t s2 = nullptr;
    static cudaEvent_t evA = nullptr, evB = nullptr;
    if (!s2) {
        cudaStreamCreateWithFlags(&s2, cudaStreamNonBlocking);
        cudaEventCreateWithFlags(&evA, cudaEventDisableTiming);
        cudaEventCreateWithFlags(&evB, cudaEventDisableTiming);
    }

    cudaEventRecord(evA, 0);
    cudaStreamWaitEvent(s2, evA, 0);
    conv_split<<<Vn * En / 1024, 256, 0, s2>>>((const float4*)embed, (uint2*)Bhi, (uint2*)Blo);
    cudaEventRecord(evB, s2);

    recurrent_kernel<<<NCTA, NTHR, DSMEM>>>(tokens, enc, mask, embed,
                                            w_ih0, w_hh0, b_ih0, b_hh0,
                                            w_ih1, w_hh1, b_ih1, b_hh1,
                                            attn_in_w, attn_out_w);
    gemm_nt_split<<<dim3(En / 128, (Bn * Tn) / 128), 256>>>(dec, out_proj_w, out_proj_b,
                                                            Ahi, Alo, Bn * Tn, En, Hn);
    cudaStreamWaitEvent(0, evB, 0);
    gemm_bf16<<<dim3((Bn * Tn) / 128, Vn / 128), 256, GSMEM2>>>(Ahi, Alo, Bhi, Blo, out, Vn, En);
}

// round 9
// speedup vs baseline: 1.2605x; 1.2605x over previous
#include <cuda_runtime.h>
#include <cuda_bf16.h>
#include <cstdint>

#define NCTA 128
#define NTHR 512
static constexpr int Bn = 32, Tn = 64, Sn = 128, Hn = 512, En = 512, Vn = 32000;
static constexpr float NEGV = -1e4f;

// ---------------- device scratch (allocation-free) ----------------
__device__ __align__(16) float g_xT[Tn][En][Bn];
__device__ __align__(16) float g_feedT[Hn][Bn];
__device__ __align__(16) float g_h0T[2][Hn][Bn];
__device__ __align__(16) float g_h1T[2][Hn][Bn];
__device__ __align__(16) float g_ctxT[Hn][Bn];
__device__ __align__(16) float g_dec[Bn * Tn][Hn];
__device__ __align__(16) float g_encq[Bn * Sn][Hn];   // enc @ attn_in_w
__device__ __align__(16) float g_attT[Hn * Hn];       // attn_in_w transposed
__device__ __nv_bfloat16 g_Ahi[Bn * Tn * En];
__device__ __nv_bfloat16 g_Alo[Bn * Tn * En];
__device__ __nv_bfloat16 g_Bhi[Vn * En];
__device__ __nv_bfloat16 g_Blo[Vn * En];
__device__ unsigned g_count;
__device__ volatile unsigned g_gen;

// ---------------- small helpers ----------------
__device__ __forceinline__ uint32_t s2u(const void* p)
{
    uint32_t a;
    asm("{ .reg .u64 t; cvta.to.shared.u64 t, %1; cvt.u32.u64 %0, t; }" : "=r"(a) : "l"(p));
    return a;
}
__device__ __forceinline__ void cp16(uint32_t s, const void* g)
{
    asm volatile("cp.async.cg.shared.global [%0], [%1], 16;" :: "r"(s), "l"(g) : "memory");
}
__device__ __forceinline__ float sigm(float x) { return 1.f / (1.f + __expf(-x)); }

__device__ __forceinline__ unsigned long long pack2(float x)
{ unsigned long long r; asm("mov.b64 %0, {%1, %1};" : "=l"(r) : "f"(x)); return r; }
__device__ __forceinline__ void ffma2(unsigned long long& d, unsigned long long a, unsigned long long b)
{ asm("fma.rn.f32x2 %0, %1, %2, %0;" : "+l"(d) : "l"(a), "l"(b)); }
__device__ __forceinline__ float2 unpack2(unsigned long long v)
{ float2 r; asm("mov.b64 {%0, %1}, %2;" : "=f"(r.x), "=f"(r.y) : "l"(v)); return r; }

// matvec segment: lane's weight row vs transposed activations act[k][32]; q=batch-quad
__device__ __forceinline__ void mvseg(const float* __restrict__ wrow,
                                      const float* __restrict__ act,
                                      int klen, int q,
                                      unsigned long long& A0, unsigned long long& A1)
{
    const char* ap = (const char*)(act + q * 4);
#pragma unroll 4
    for (int k0 = 0; k0 < klen; k0 += 8) {
        float4 w0 = __ldg((const float4*)(wrow + k0));
        float4 w1 = __ldg((const float4*)(wrow + k0 + 4));
        ulonglong2 av[8];
#pragma unroll
        for (int kk = 0; kk < 8; kk++)
            av[kk] = __ldca((const ulonglong2*)(ap + (size_t)(k0 + kk) * 128));
        float ws[8] = {w0.x, w0.y, w0.z, w0.w, w1.x, w1.y, w1.z, w1.w};
#pragma unroll
        for (int kk = 0; kk < 8; kk++) {
            unsigned long long wp = pack2(ws[kk]);
            ffma2(A0, wp, av[kk].x);
            ffma2(A1, wp, av[kk].y);
        }
    }
}

// ---------------- grid barrier (all 128 CTAs co-resident) ----------------
__device__ __forceinline__ void gbar()
{
    __threadfence();
    __syncthreads();
    if (threadIdx.x == 0) {
        unsigned g = g_gen;
        unsigned a = atomicAdd(&g_count, 1u);
        if (a == NCTA - 1u) {
            g_count = 0u;
            __threadfence();
            g_gen = g + 1u;
        } else {
            while (g_gen == g) { }
        }
    }
    __syncthreads();
    __threadfence();
}

// ---------------- persistent recurrence (512 threads: 16 warps) ----------------
__global__ void __launch_bounds__(NTHR, 1)
recurrent_kernel(const int* __restrict__ tokens, const float* __restrict__ enc,
                 const int* __restrict__ mask, const float* __restrict__ embed,
                 const float* __restrict__ w_ih0, const float* __restrict__ w_hh0,
                 const float* __restrict__ b_ih0, const float* __restrict__ b_hh0,
                 const float* __restrict__ w_ih1, const float* __restrict__ w_hh1,
                 const float* __restrict__ b_ih1, const float* __restrict__ b_hh1,
                 const float* __restrict__ attn_out_w)
{
    const int tid = threadIdx.x, cta = blockIdx.x;
    const int warp = tid >> 5, lane = tid & 31;
    const int gtid = cta * NTHR + tid;

    __shared__ __align__(16) float sA[4][4][4][32];   // [kq][g][r][batch]
    __shared__ __align__(16) float s_q[512];
    __shared__ float s_sc[128];
    __shared__ float s_red[32];

    // ---- init recurrent state ----
    for (int i = gtid; i < Hn * Bn; i += NCTA * NTHR) {
        (&g_feedT[0][0])[i] = 0.f;
        (&g_h0T[0][0][0])[i] = 0.f; (&g_h0T[1][0][0])[i] = 0.f;
        (&g_h1T[0][0][0])[i] = 0.f; (&g_h1T[1][0][0])[i] = 0.f;
    }
    // ---- embed gather+transpose (2048 warps == 2048 (t,b) pairs) ----
    {
        int p = gtid >> 5;
        int b = p & 31, t0 = p >> 5;
        int tok = __ldg(tokens + b * Tn + t0);
        const float4* er = (const float4*)(embed + (size_t)tok * En);
#pragma unroll
        for (int i = 0; i < 4; i++) {
            float4 v = __ldg(er + i * 32 + lane);
            int e = (i * 32 + lane) * 4;
            g_xT[t0][e][b] = v.x; g_xT[t0][e + 1][b] = v.y;
            g_xT[t0][e + 2][b] = v.z; g_xT[t0][e + 3][b] = v.w;
        }
    }
    gbar();

    // warp roles: g = row-group, kq = K-quarter; lane: r = gate/seg, q = batch-quad
    const int g = warp >> 2, kq = warp & 3;
    const int r = lane >> 3, q = lane & 7;
    const int j = cta * 4 + g;

    const size_t rowAB = (size_t)(j + 512 * r);
    const float* wih0r = w_ih0 + rowAB * 1024;
    const float* whh0r = w_hh0 + rowAB * 512;
    const float* wih1r = w_ih1 + rowAB * 512;
    const float* whh1r = w_hh1 + rowAB * 512;

    float c0r = 0.f, c1r = 0.f;
    float biA[4], biB[4];
    if (tid < 128) {
        int jj = tid >> 5, ju = cta * 4 + jj;
#pragma unroll
        for (int rr = 0; rr < 4; rr++) {
            biA[rr] = __ldg(b_ih0 + ju + 512 * rr) + __ldg(b_hh0 + ju + 512 * rr);
            biB[rr] = __ldg(b_ih1 + ju + 512 * rr) + __ldg(b_hh1 + ju + 512 * rr);
        }
    }

    for (int t = 0; t < Tn; t++) {
        const int cur = t & 1, prv = cur ^ 1;

        // ---------- Phase A: LSTM layer 0 gates (K = x512|feed512|h0 512, kq-split) ----------
        {
            unsigned long long A0 = 0ull, A1 = 0ull;
            const int ko = kq * 128;
            mvseg(wih0r + ko,       &g_xT[t][ko][0],      128, q, A0, A1);
            mvseg(wih0r + 512 + ko, &g_feedT[ko][0],      128, q, A0, A1);
            mvseg(whh0r + ko,       &g_h0T[prv][ko][0],   128, q, A0, A1);
            float2 v0 = unpack2(A0), v1 = unpack2(A1);
            *(float4*)&sA[kq][g][r][q * 4] = make_float4(v0.x, v0.y, v1.x, v1.y);
            __syncthreads();
            if (tid < 128) {
                int b = tid & 31, jj = tid >> 5;
                float gi = sA[0][jj][0][b] + sA[1][jj][0][b] + sA[2][jj][0][b] + sA[3][jj][0][b] + biA[0];
                float gf = sA[0][jj][1][b] + sA[1][jj][1][b] + sA[2][jj][1][b] + sA[3][jj][1][b] + biA[1];
                float gg = sA[0][jj][2][b] + sA[1][jj][2][b] + sA[2][jj][2][b] + sA[3][jj][2][b] + biA[2];
                float go = sA[0][jj][3][b] + sA[1][jj][3][b] + sA[2][jj][3][b] + sA[3][jj][3][b] + biA[3];
                c0r = sigm(gf) * c0r + sigm(gi) * tanhf(gg);
                g_h0T[cur][cta * 4 + jj][b] = sigm(go) * tanhf(c0r);
            }
        }
        gbar();

        // ---------- Phase B: LSTM layer 1 gates (K = h0cur 512 | h1prv 512) ----------
        {
            unsigned long long A0 = 0ull, A1 = 0ull;
            const int ko = kq * 128;
            mvseg(wih1r + ko, &g_h0T[cur][ko][0], 128, q, A0, A1);
            mvseg(whh1r + ko, &g_h1T[prv][ko][0], 128, q, A0, A1);
            float2 v0 = unpack2(A0), v1 = unpack2(A1);
            *(float4*)&sA[kq][g][r][q * 4] = make_float4(v0.x, v0.y, v1.x, v1.y);
            __syncthreads();
            if (tid < 128) {
                int b = tid & 31, jj = tid >> 5;
                float gi = sA[0][jj][0][b] + sA[1][jj][0][b] + sA[2][jj][0][b] + sA[3][jj][0][b] + biB[0];
                float gf = sA[0][jj][1][b] + sA[1][jj][1][b] + sA[2][jj][1][b] + sA[3][jj][1][b] + biB[1];
                float gg = sA[0][jj][2][b] + sA[1][jj][2][b] + sA[2][jj][2][b] + sA[3][jj][2][b] + biB[2];
                float go = sA[0][jj][3][b] + sA[1][jj][3][b] + sA[2][jj][3][b] + sA[3][jj][3][b] + biB[3];
                c1r = sigm(gf) * c1r + sigm(gi) * tanhf(gg);
                g_h1T[cur][cta * 4 + jj][b] = sigm(go) * tanhf(c1r);
            }
        }
        gbar();

        // ---------- Phase D: scores (encq·h1) -> softmax -> ctx (one CTA per batch) ----------
        if (cta < Bn) {
            const int b = cta;
            s_q[tid] = __ldca(&g_h1T[cur][tid][b]);
            __syncthreads();
#pragma unroll
            for (int i = 0; i < 8; i++) {
                int sp = warp * 8 + i;
                const float4* er = (const float4*)(g_encq[(size_t)b * Sn + sp]);
                const float4* qr = (const float4*)s_q;
                float acc = 0.f;
#pragma unroll
                for (int c4 = 0; c4 < 4; c4++) {
                    float4 e = __ldca(er + c4 * 32 + lane);
                    float4 q4 = qr[c4 * 32 + lane];
                    acc += e.x * q4.x + e.y * q4.y + e.z * q4.z + e.w * q4.w;
                }
#pragma unroll
                for (int o = 16; o; o >>= 1) acc += __shfl_xor_sync(~0u, acc, o);
                if (lane == 0)
                    s_sc[sp] = (__ldg(mask + b * Sn + sp) == 0) ? NEGV : acc;
            }
            __syncthreads();
            float mv = (tid < 128) ? s_sc[tid] : -3e38f;
#pragma unroll
            for (int o = 16; o; o >>= 1) mv = fmaxf(mv, __shfl_xor_sync(~0u, mv, o));
            if (tid < 128 && lane == 0) s_red[warp] = mv;
            __syncthreads();
            if (tid == 0) {
                float m = s_red[0];
                for (int w = 1; w < 4; w++) m = fmaxf(m, s_red[w]);
                s_red[16] = m;
            }
            __syncthreads();
            float ev = 0.f;
            if (tid < 128) ev = __expf(s_sc[tid] - s_red[16]);
            float sv = ev;
#pragma unroll
            for (int o = 16; o; o >>= 1) sv += __shfl_xor_sync(~0u, sv, o);
            if (tid < 128 && lane == 0) s_red[warp] = sv;
            __syncthreads();
            if (tid == 0) {
                float s = 0.f;
                for (int w = 0; w < 4; w++) s += s_red[w];
                s_red[17] = 1.f / s;
            }
            __syncthreads();
            if (tid < 128) s_sc[tid] = ev * s_red[17];
            __syncthreads();
            {
                int h = tid;
                const float* ep = enc + (size_t)b * Sn * Hn + h;
                float a0 = 0.f, a1 = 0.f;
#pragma unroll 8
                for (int s = 0; s < 64; s++) {
                    a0 += s_sc[s] * __ldg(ep + s * Hn);
                    a1 += s_sc[s + 64] * __ldg(ep + (s + 64) * Hn);
                }
                g_ctxT[h][b] = a0 + a1;
            }
        }
        gbar();

        // ---------- Phase E: input_feed = tanh(attn_out_w @ [ctx512; h1cur512]) ----------
        {
            unsigned long long A0 = 0ull, A1 = 0ull;
            const int seg = kq * 4 + r;   // 16 segments of 64
            const float* src = (seg < 8) ? &g_ctxT[seg * 64][0]
                                         : &g_h1T[cur][(seg - 8) * 64][0];
            mvseg(attn_out_w + (size_t)j * 1024 + seg * 64, src, 64, q, A0, A1);
            float2 v0 = unpack2(A0), v1 = unpack2(A1);
            *(float4*)&sA[kq][g][r][q * 4] = make_float4(v0.x, v0.y, v1.x, v1.y);
            __syncthreads();
            if (tid < 128) {
                int b = tid & 31, jj = tid >> 5;
                float s = 0.f;
#pragma unroll
                for (int kk = 0; kk < 4; kk++)
#pragma unroll
                    for (int rr = 0; rr < 4; rr++) s += sA[kk][jj][rr][b];
                float f = tanhf(s);
                g_feedT[cta * 4 + jj][b] = f;
                g_dec[b * Tn + t][cta * 4 + jj] = f;
            }
        }
        gbar();
    }
}

// ---------------- 512x512 transpose (attn_in_w -> g_attT) ----------------
__global__ void __launch_bounds__(256)
trans512(const float* __restrict__ src, float* __restrict__ dst)
{
    __shared__ float tile[32][33];
    int bx = blockIdx.x * 32, by = blockIdx.y * 32;
    int tx = threadIdx.x & 31, ty = threadIdx.x >> 5;   // 32x8
#pragma unroll
    for (int i = 0; i < 4; i++)
        tile[ty + i * 8][tx] = __ldg(src + (size_t)(by + ty + i * 8) * 512 + bx + tx);
    __syncthreads();
#pragma unroll
    for (int i = 0; i < 4; i++)
        dst[(size_t)(bx + ty + i * 8) * 512 + by + tx] = tile[tx][ty + i * 8];
}

// ---------------- SIMT f32x2 gemm: C = A @ W^T (+bias), fp32 out ----------------
__global__ void __launch_bounds__(256)
gemm_nt(const float* __restrict__ A, const float* __restrict__ W,
        const float* __restrict__ bias, float* __restrict__ C,
        int M, int N, int K)
{
    __shared__ __align__(16) float As[16][128];
    __shared__ __align__(16) float Ws[16][128];
    const int m0 = blockIdx.y * 128, n0 = blockIdx.x * 128;
    const int tid = threadIdx.x;
    const int tx = tid & 15, ty = tid >> 4;
    const int lrow = tid >> 1, lcol = (tid & 1) * 8;

    unsigned long long acc2[8][4];
#pragma unroll
    for (int i = 0; i < 8; i++)
#pragma unroll
        for (int jj = 0; jj < 4; jj++) acc2[i][jj] = 0ull;

    const float* Aload = A + (size_t)(m0 + lrow) * K + lcol;
    const float* Wload = W + (size_t)(n0 + lrow) * K + lcol;

    for (int k0 = 0; k0 < K; k0 += 16) {
        float4 a0 = __ldg((const float4*)(Aload + k0));
        float4 a1 = __ldg((const float4*)(Aload + k0 + 4));
        float4 w0 = __ldg((const float4*)(Wload + k0));
        float4 w1 = __ldg((const float4*)(Wload + k0 + 4));
        __syncthreads();
        As[lcol + 0][lrow] = a0.x; As[lcol + 1][lrow] = a0.y;
        As[lcol + 2][lrow] = a0.z; As[lcol + 3][lrow] = a0.w;
        As[lcol + 4][lrow] = a1.x; As[lcol + 5][lrow] = a1.y;
        As[lcol + 6][lrow] = a1.z; As[lcol + 7][lrow] = a1.w;
        Ws[lcol + 0][lrow] = w0.x; Ws[lcol + 1][lrow] = w0.y;
        Ws[lcol + 2][lrow] = w0.z; Ws[lcol + 3][lrow] = w0.w;
        Ws[lcol + 4][lrow] = w1.x; Ws[lcol + 5][lrow] = w1.y;
        Ws[lcol + 6][lrow] = w1.z; Ws[lcol + 7][lrow] = w1.w;
        __syncthreads();
#pragma unroll
        for (int kk = 0; kk < 16; kk++) {
            float4 av0 = *(const float4*)&As[kk][ty * 8];
            float4 av1 = *(const float4*)&As[kk][ty * 8 + 4];
            const ulonglong2* wp = (const ulonglong2*)&Ws[kk][tx * 8];
            ulonglong2 b01 = wp[0], b23 = wp[1];
            float a8[8] = {av0.x, av0.y, av0.z, av0.w, av1.x, av1.y, av1.z, av1.w};
#pragma unroll
            for (int i = 0; i < 8; i++) {
                unsigned long long a2 = pack2(a8[i]);
                ffma2(acc2[i][0], a2, b01.x);
                ffma2(acc2[i][1], a2, b01.y);
                ffma2(acc2[i][2], a2, b23.x);
                ffma2(acc2[i][3], a2, b23.y);
            }
        }
    }
#pragma unroll
    for (int i = 0; i < 8; i++) {
        float* Crow = C + (size_t)(m0 + ty * 8 + i) * N + n0 + tx * 8;
#pragma unroll
        for (int jj = 0; jj < 4; jj++) {
            float2 v = unpack2(acc2[i][jj]);
            if (bias) {
                v.x += __ldg(bias + n0 + tx * 8 + 2 * jj);
                v.y += __ldg(bias + n0 + tx * 8 + 2 * jj + 1);
            }
            *(float2*)(Crow + 2 * jj) = v;
        }
    }
}

// ---------------- SIMT f32x2 gemm (out_proj) -> bf16 hi/lo ----------------
__device__ __forceinline__ void split_bf16(float v, __nv_bfloat16& h, __nv_bfloat16& l)
{
    h = __float2bfloat16(v);
    l = __float2bfloat16(v - __bfloat162float(h));
}

__global__ void __launch_bounds__(256)
gemm_nt_split(const float* __restrict__ A, const float* __restrict__ W,
              const float* __restrict__ bias,
              __nv_bfloat16* __restrict__ Chi, __nv_bfloat16* __restrict__ Clo,
              int M, int N, int K)
{
    __shared__ __align__(16) float As[16][128];
    __shared__ __align__(16) float Ws[16][128];
    const int m0 = blockIdx.y * 128, n0 = blockIdx.x * 128;
    const int tid = threadIdx.x;
    const int tx = tid & 15, ty = tid >> 4;
    const int lrow = tid >> 1, lcol = (tid & 1) * 8;

    unsigned long long acc2[8][4];
#pragma unroll
    for (int i = 0; i < 8; i++)
#pragma unroll
        for (int jj = 0; jj < 4; jj++) acc2[i][jj] = 0ull;

    const float* Aload = A + (size_t)(m0 + lrow) * K + lcol;
    const float* Wload = W + (size_t)(n0 + lrow) * K + lcol;

    for (int k0 = 0; k0 < K; k0 += 16) {
        float4 a0 = __ldg((const float4*)(Aload + k0));
        float4 a1 = __ldg((const float4*)(Aload + k0 + 4));
        float4 w0 = __ldg((const float4*)(Wload + k0));
        float4 w1 = __ldg((const float4*)(Wload + k0 + 4));
        __syncthreads();
        As[lcol + 0][lrow] = a0.x; As[lcol + 1][lrow] = a0.y;
        As[lcol + 2][lrow] = a0.z; As[lcol + 3][lrow] = a0.w;
        As[lcol + 4][lrow] = a1.x; As[lcol + 5][lrow] = a1.y;
        As[lcol + 6][lrow] = a1.z; As[lcol + 7][lrow] = a1.w;
        Ws[lcol + 0][lrow] = w0.x; Ws[lcol + 1][lrow] = w0.y;
        Ws[lcol + 2][lrow] = w0.z; Ws[lcol + 3][lrow] = w0.w;
        Ws[lcol + 4][lrow] = w1.x; Ws[lcol + 5][lrow] = w1.y;
        Ws[lcol + 6][lrow] = w1.z; Ws[lcol + 7][lrow] = w1.w;
        __syncthreads();
#pragma unroll
        for (int kk = 0; kk < 16; kk++) {
            float4 av0 = *(const float4*)&As[kk][ty * 8];
            float4 av1 = *(const float4*)&As[kk][ty * 8 + 4];
            const ulonglong2* wp = (const ulonglong2*)&Ws[kk][tx * 8];
            ulonglong2 b01 = wp[0], b23 = wp[1];
            float a8[8] = {av0.x, av0.y, av0.z, av0.w, av1.x, av1.y, av1.z, av1.w};
#pragma unroll
            for (int i = 0; i < 8; i++) {
                unsigned long long a2 = pack2(a8[i]);
                ffma2(acc2[i][0], a2, b01.x);
                ffma2(acc2[i][1], a2, b01.y);
                ffma2(acc2[i][2], a2, b23.x);
                ffma2(acc2[i][3], a2, b23.y);
            }
        }
    }
#pragma unroll
    for (int i = 0; i < 8; i++) {
        size_t rowoff = (size_t)(m0 + ty * 8 + i) * N + n0 + tx * 8;
        unsigned short tmph[8], tmpl[8];
#pragma unroll
        for (int jj = 0; jj < 4; jj++) {
            float2 v = unpack2(acc2[i][jj]);
            v.x += __ldg(bias + n0 + tx * 8 + 2 * jj);
            v.y += __ldg(bias + n0 + tx * 8 + 2 * jj + 1);
            __nv_bfloat16 h0, l0, h1, l1;
            split_bf16(v.x, h0, l0);
            split_bf16(v.y, h1, l1);
            tmph[2 * jj] = __bfloat16_as_ushort(h0); tmph[2 * jj + 1] = __bfloat16_as_ushort(h1);
            tmpl[2 * jj] = __bfloat16_as_ushort(l0); tmpl[2 * jj + 1] = __bfloat16_as_ushort(l1);
        }
        uint2 H, L, H2, L2;
        H.x = (uint32_t)tmph[0] | ((uint32_t)tmph[1] << 16);
        H.y = (uint32_t)tmph[2] | ((uint32_t)tmph[3] << 16);
        L.x = (uint32_t)tmpl[0] | ((uint32_t)tmpl[1] << 16);
        L.y = (uint32_t)tmpl[2] | ((uint32_t)tmpl[3] << 16);
        H2.x = (uint32_t)tmph[4] | ((uint32_t)tmph[5] << 16);
        H2.y = (uint32_t)tmph[6] | ((uint32_t)tmph[7] << 16);
        L2.x = (uint32_t)tmpl[4] | ((uint32_t)tmpl[5] << 16);
        L2.y = (uint32_t)tmpl[6] | ((uint32_t)tmpl[7] << 16);
        *(uint2*)(Chi + rowoff) = H;  *(uint2*)(Chi + rowoff + 4) = H2;
        *(uint2*)(Clo + rowoff) = L;  *(uint2*)(Clo + rowoff + 4) = L2;
    }
}

// ---------------- fp32 -> bf16 hi/lo split (embed) ----------------
__global__ void __launch_bounds__(256)
conv_split(const float4* __restrict__ src, uint2* __restrict__ hi, uint2* __restrict__ lo)
{
    int i = blockIdx.x * 256 + threadIdx.x;
    float4 v = __ldg(src + i);
    __nv_bfloat16 h0, l0, h1, l1, h2, l2, h3, l3;
    split_bf16(v.x, h0, l0); split_bf16(v.y, h1, l1);
    split_bf16(v.z, h2, l2); split_bf16(v.w, h3, l3);
    uint2 H, L;
    H.x = (uint32_t)__bfloat16_as_ushort(h0) | ((uint32_t)__bfloat16_as_ushort(h1) << 16);
    H.y = (uint32_t)__bfloat16_as_ushort(h2) | ((uint32_t)__bfloat16_as_ushort(h3) << 16);
    L.x = (uint32_t)__bfloat16_as_ushort(l0) | ((uint32_t)__bfloat16_as_ushort(l1) << 16);
    L.y = (uint32_t)__bfloat16_as_ushort(l2) | ((uint32_t)__bfloat16_as_ushort(l3) << 16);
    hi[i] = H; lo[i] = L;
}

// ---------------- mma.sync bf16 3-pass GEMM: C = A @ B^T ----------------
static constexpr int KC = 32;
static constexpr int NCHUNK = En / KC;
static constexpr int ROWB = 80;
static constexpr int MATB = 128 * ROWB;
static constexpr int STAGEB = 4 * MATB;
static constexpr int GSMEM2 = 2 * STAGEB;

__device__ __forceinline__ void ldmA(uint32_t* r, uint32_t addr)
{
    asm volatile("ldmatrix.sync.aligned.m8n8.x4.shared.b16 {%0,%1,%2,%3}, [%4];"
                 : "=r"(r[0]), "=r"(r[1]), "=r"(r[2]), "=r"(r[3]) : "r"(addr));
}
__device__ __forceinline__ void ldmB(uint32_t* r, uint32_t addr)
{
    asm volatile("ldmatrix.sync.aligned.m8n8.x2.shared.b16 {%0,%1}, [%2];"
                 : "=r"(r[0]), "=r"(r[1]) : "r"(addr));
}
__device__ __forceinline__ void mma16816(float* d, const uint32_t* a, const uint32_t* b)
{
    asm volatile("mma.sync.aligned.m16n8k16.row.col.f32.bf16.bf16.f32 "
                 "{%0,%1,%2,%3}, {%4,%5,%6,%7}, {%8,%9}, {%0,%1,%2,%3};"
                 : "+f"(d[0]), "+f"(d[1]), "+f"(d[2]), "+f"(d[3])
                 : "r"(a[0]), "r"(a[1]), "r"(a[2]), "r"(a[3]), "r"(b[0]), "r"(b[1]));
}

__global__ void __launch_bounds__(256, 2)
gemm_bf16(const __nv_bfloat16* __restrict__ Ahi, const __nv_bfloat16* __restrict__ Alo,
          const __nv_bfloat16* __restrict__ Bhi, const __nv_bfloat16* __restrict__ Blo,
          float* __restrict__ C, int N, int K)
{
    extern __shared__ char smem[];
    const uint32_t su = s2u(smem);
    const int tid = threadIdx.x, wid = tid >> 5, lane = tid & 31;
    const int m0 = blockIdx.x * 128, n0 = blockIdx.y * 128;
    const int wm = wid & 1, wn = wid >> 1;

    const int ci0 = tid;
    auto load_stage = [&](int chunk) {
        const uint32_t sb = su + (chunk & 1) * STAGEB;
#pragma unroll
        for (int r8 = 0; r8 < 8; r8++) {
            int ci = ci0 + r8 * 256;
            int mat = ci >> 9, rem = ci & 511;
            int row = rem >> 2, seg = rem & 3;
            const __nv_bfloat16* g;
            if (mat == 0)      g = Ahi + (size_t)(m0 + row) * K + chunk * KC + seg * 8;
            else if (mat == 1) g = Alo + (size_t)(m0 + row) * K + chunk * KC + seg * 8;
            else if (mat == 2) g = Bhi + (size_t)(n0 + row) * K + chunk * KC + seg * 8;
            else               g = Blo + (size_t)(n0 + row) * K + chunk * KC + seg * 8;
            cp16(sb + mat * MATB + row * ROWB + seg * 16, g);
        }
        asm volatile("cp.async.commit_group;" ::: "memory");
    };

    float acc[4][4][4];
#pragma unroll
    for (int i = 0; i < 4; i++)
#pragma unroll
        for (int jj = 0; jj < 4; jj++)
#pragma unroll
            for (int k = 0; k < 4; k++) acc[i][jj][k] = 0.f;

    load_stage(0);
    load_stage(1);

    for (int c = 0; c < NCHUNK; c++) {
        if (c < NCHUNK - 1) asm volatile("cp.async.wait_group 1;" ::: "memory");
        else                asm volatile("cp.async.wait_group 0;" ::: "memory");
        __syncthreads();
        const uint32_t sb = su + (c & 1) * STAGEB;
        const uint32_t aHiB = sb,            aLoB = sb + MATB;
        const uint32_t bHiB = sb + 2 * MATB, bLoB = sb + 3 * MATB;
#pragma unroll
        for (int ks = 0; ks < 2; ks++) {
            const uint32_t aoff = (uint32_t)((wm * 64 + (lane & 15)) * ROWB
                                             + (ks * 16 + (lane >> 4) * 8) * 2);
            const int l = lane & 15;
            const uint32_t boff = (uint32_t)((wn * 32 + (l & 7)) * ROWB
                                             + (ks * 16 + (l >> 3) * 8) * 2);
            uint32_t ah[4][4], al[4][4], bh[4][2], bl[4][2];
#pragma unroll
            for (int mi = 0; mi < 4; mi++) {
                ldmA(ah[mi], aHiB + aoff + mi * 16 * ROWB);
                ldmA(al[mi], aLoB + aoff + mi * 16 * ROWB);
            }
#pragma unroll
            for (int ni = 0; ni < 4; ni++) {
                ldmB(bh[ni], bHiB + boff + ni * 8 * ROWB);
                ldmB(bl[ni], bLoB + boff + ni * 8 * ROWB);
            }
#pragma unroll
            for (int mi = 0; mi < 4; mi++)
#pragma unroll
                for (int ni = 0; ni < 4; ni++) {
                    mma16816(acc[mi][ni], ah[mi], bh[ni]);
                    mma16816(acc[mi][ni], ah[mi], bl[ni]);
                    mma16816(acc[mi][ni], al[mi], bh[ni]);
                }
        }
        __syncthreads();
        if (c + 2 < NCHUNK) load_stage(c + 2);
    }

    const int mbase = m0 + wm * 64 + (lane >> 2);
    const int nbase = n0 + wn * 32 + (lane & 3) * 2;
#pragma unroll
    for (int mi = 0; mi < 4; mi++)
#pragma unroll
        for (int ni = 0; ni < 4; ni++) {
            float* p0 = C + (size_t)(mbase + mi * 16) * N + nbase + ni * 8;
            float* p1 = C + (size_t)(mbase + mi * 16 + 8) * N + nbase + ni * 8;
            *(float2*)p0 = make_float2(acc[mi][ni][0], acc[mi][ni][1]);
            *(float2*)p1 = make_float2(acc[mi][ni][2], acc[mi][ni][3]);
        }
}

extern "C" void kernel_launch(void* const* d_in, const int* in_sizes, int n_in,
                              void* d_out, int out_size)
{
    const int*   tokens     = (const int*)d_in[0];
    const float* enc        = (const float*)d_in[1];
    const int*   mask       = (const int*)d_in[2];
    const float* embed      = (const float*)d_in[3];
    const float* w_ih0      = (const float*)d_in[4];
    const float* w_hh0      = (const float*)d_in[5];
    const float* b_ih0      = (const float*)d_in[6];
    const float* b_hh0      = (const float*)d_in[7];
    const float* w_ih1      = (const float*)d_in[8];
    const float* w_hh1      = (const float*)d_in[9];
    const float* b_ih1      = (const float*)d_in[10];
    const float* b_hh1      = (const float*)d_in[11];
    const float* attn_in_w  = (const float*)d_in[12];
    const float* attn_out_w = (const float*)d_in[13];
    const float* out_proj_w = (const float*)d_in[14];
    const float* out_proj_b = (const float*)d_in[15];
    float* out = (float*)d_out;

    float *dec, *encq, *attT;
    __nv_bfloat16 *Ahi, *Alo, *Bhi, *Blo;
    cudaGetSymbolAddress((void**)&dec, g_dec);
    cudaGetSymbolAddress((void**)&encq, g_encq);
    cudaGetSymbolAddress((void**)&attT, g_attT);
    cudaGetSymbolAddress((void**)&Ahi, g_Ahi);
    cudaGetSymbolAddress((void**)&Alo, g_Alo);
    cudaGetSymbolAddress((void**)&Bhi, g_Bhi);
    cudaGetSymbolAddress((void**)&Blo, g_Blo);

    cudaFuncSetAttribute(gemm_bf16, cudaFuncAttributeMaxDynamicSharedMemorySize, GSMEM2);

    static cudaStream_t s2 = nullptr;
    static cudaEvent_t evA = nullptr, evB = nullptr;
    if (!s2) {
        cudaStreamCreateWithFlags(&s2, cudaStreamNonBlocking);
        cudaEventCreateWithFlags(&evA, cudaEventDisableTiming);
        cudaEventCreateWithFlags(&evB, cudaEventDisableTiming);
    }

    // side stream: embed hi/lo conversion (independent; overlaps recurrence)
    cudaEventRecord(evA, 0);
    cudaStreamWaitEvent(s2, evA, 0);
    conv_split<<<Vn * En / 1024, 256, 0, s2>>>((const float4*)embed, (uint2*)Bhi, (uint2*)Blo);
    cudaEventRecord(evB, s2);

    // encq = enc @ attn_in_w (via transpose + gemm_nt) — replaces phase C
    trans512<<<dim3(16, 16), 256>>>(attn_in_w, attT);
    gemm_nt<<<dim3(Hn / 128, (Bn * Sn) / 128), 256>>>(enc, attT, nullptr, encq,
                                                      Bn * Sn, Hn, Hn);
    recurrent_kernel<<<NCTA, NTHR>>>(tokens, enc, mask, embed,
                                     w_ih0, w_hh0, b_ih0, b_hh0,
                                     w_ih1, w_hh1, b_ih1, b_hh1,
                                     attn_out_w);
    gemm_nt_split<<<dim3(En / 128, (Bn * Tn) / 128), 256>>>(dec, out_proj_w, out_proj_b,
                                                            Ahi, Alo, Bn * Tn, En, Hn);
    cudaStreamWaitEvent(0, evB, 0);
    gemm_bf16<<<dim3((Bn * Tn) / 128, Vn / 128), 256, GSMEM2>>>(Ahi, Alo, Bhi, Blo, out, Vn, En);
}

// round 10
// speedup vs baseline: 1.3273x; 1.0530x over previous
#include <cuda_runtime.h>
#include <cuda_bf16.h>
#include <cstdint>

#define NCTA 128
#define NTHR 512
static constexpr int Bn = 32, Tn = 64, Sn = 128, Hn = 512, En = 512, Vn = 32000;
static constexpr float NEGV = -1e4f;

// ---------------- device scratch (allocation-free) ----------------
__device__ __align__(16) float g_xT[Tn][En][Bn];
__device__ __align__(16) float g_feedT[Hn][Bn];
__device__ __align__(16) float g_h0T[2][Hn][Bn];
__device__ __align__(16) float g_h1T[2][Hn][Bn];
__device__ __align__(16) float g_ctxT[Hn][Bn];
__device__ __align__(16) float g_dec[Bn * Tn][Hn];
__device__ __align__(16) float g_encq[Bn * Sn][Hn];   // enc @ attn_in_w
__device__ __align__(16) float g_attT[Hn * Hn];       // attn_in_w transposed
__device__ __nv_bfloat16 g_Ahi[Bn * Tn * En];
__device__ __nv_bfloat16 g_Alo[Bn * Tn * En];
__device__ __nv_bfloat16 g_Bhi[Vn * En];
__device__ __nv_bfloat16 g_Blo[Vn * En];
__device__ unsigned g_count;
__device__ volatile unsigned g_gen;

// ---------------- small helpers ----------------
__device__ __forceinline__ uint32_t s2u(const void* p)
{
    uint32_t a;
    asm("{ .reg .u64 t; cvta.to.shared.u64 t, %1; cvt.u32.u64 %0, t; }" : "=r"(a) : "l"(p));
    return a;
}
__device__ __forceinline__ void cp16(uint32_t s, const void* g)
{
    asm volatile("cp.async.cg.shared.global [%0], [%1], 16;" :: "r"(s), "l"(g) : "memory");
}
__device__ __forceinline__ float sigm(float x) { return 1.f / (1.f + __expf(-x)); }

__device__ __forceinline__ unsigned long long pack2(float x)
{ unsigned long long r; asm("mov.b64 %0, {%1, %1};" : "=l"(r) : "f"(x)); return r; }
__device__ __forceinline__ void ffma2(unsigned long long& d, unsigned long long a, unsigned long long b)
{ asm("fma.rn.f32x2 %0, %1, %2, %0;" : "+l"(d) : "l"(a), "l"(b)); }
__device__ __forceinline__ float2 unpack2(unsigned long long v)
{ float2 r; asm("mov.b64 {%0, %1}, %2;" : "=f"(r.x), "=f"(r.y) : "l"(v)); return r; }

// matvec segment: weight row from SMEM (LDS) vs transposed activations in L2 [k][32]
__device__ __forceinline__ void mvseg(const float* __restrict__ wrow,   // smem
                                      const float* __restrict__ act,    // global
                                      int klen, int q,
                                      unsigned long long& A0, unsigned long long& A1)
{
    const char* ap = (const char*)(act + q * 4);
#pragma unroll 4
    for (int k0 = 0; k0 < klen; k0 += 8) {
        float4 w0 = *(const float4*)(wrow + k0);
        float4 w1 = *(const float4*)(wrow + k0 + 4);
        ulonglong2 av[8];
#pragma unroll
        for (int kk = 0; kk < 8; kk++)
            av[kk] = __ldca((const ulonglong2*)(ap + (size_t)(k0 + kk) * 128));
        float ws[8] = {w0.x, w0.y, w0.z, w0.w, w1.x, w1.y, w1.z, w1.w};
#pragma unroll
        for (int kk = 0; kk < 8; kk++) {
            unsigned long long wp = pack2(ws[kk]);
            ffma2(A0, wp, av[kk].x);
            ffma2(A1, wp, av[kk].y);
        }
    }
}

// ---------------- grid barrier (all 128 CTAs co-resident) ----------------
__device__ __forceinline__ void gbar()
{
    __threadfence();
    __syncthreads();
    if (threadIdx.x == 0) {
        unsigned g = g_gen;
        unsigned a = atomicAdd(&g_count, 1u);
        if (a == NCTA - 1u) {
            g_count = 0u;
            __threadfence();
            g_gen = g + 1u;
        } else {
            while (g_gen == g) { }
        }
    }
    __syncthreads();
    __threadfence();
}

// dynamic smem layout for recurrent kernel (weight slices, padded rows)
static constexpr int WA_STR = 1540;   // 1536 + 4 pad
static constexpr int WB_STR = 1028;   // 1024 + 4 pad
static constexpr int WE_STR = 1028;
static constexpr int OFF_WA = 0;
static constexpr int OFF_WB = OFF_WA + 16 * WA_STR;   // floats
static constexpr int OFF_WE = OFF_WB + 16 * WB_STR;
static constexpr int DSMEM = (OFF_WE + 4 * WE_STR) * 4;   // bytes = 180800

// ---------------- persistent recurrence (512 threads: 16 warps) ----------------
__global__ void __launch_bounds__(NTHR, 1)
recurrent_kernel(const int* __restrict__ tokens, const float* __restrict__ enc,
                 const int* __restrict__ mask, const float* __restrict__ embed,
                 const float* __restrict__ w_ih0, const float* __restrict__ w_hh0,
                 const float* __restrict__ b_ih0, const float* __restrict__ b_hh0,
                 const float* __restrict__ w_ih1, const float* __restrict__ w_hh1,
                 const float* __restrict__ b_ih1, const float* __restrict__ b_hh1,
                 const float* __restrict__ attn_out_w)
{
    extern __shared__ __align__(16) float wsm[];
    float* wA = wsm + OFF_WA;
    float* wB = wsm + OFF_WB;
    float* wE = wsm + OFF_WE;

    const int tid = threadIdx.x, cta = blockIdx.x;
    const int warp = tid >> 5, lane = tid & 31;
    const int gtid = cta * NTHR + tid;

    __shared__ __align__(16) float sA[4][4][4][32];   // [kq][g][r][batch]
    __shared__ __align__(16) float s_q[512];
    __shared__ float s_sc[128];
    __shared__ float s_red[32];

    // ---- init recurrent state ----
    for (int i = gtid; i < Hn * Bn; i += NCTA * NTHR) {
        (&g_feedT[0][0])[i] = 0.f;
        (&g_h0T[0][0][0])[i] = 0.f; (&g_h0T[1][0][0])[i] = 0.f;
        (&g_h1T[0][0][0])[i] = 0.f; (&g_h1T[1][0][0])[i] = 0.f;
    }
    // ---- embed gather+transpose (2048 warps == 2048 (t,b) pairs) ----
    {
        int p = gtid >> 5;
        int b = p & 31, t0 = p >> 5;
        int tok = __ldg(tokens + b * Tn + t0);
        const float4* er = (const float4*)(embed + (size_t)tok * En);
#pragma unroll
        for (int i = 0; i < 4; i++) {
            float4 v = __ldg(er + i * 32 + lane);
            int e = (i * 32 + lane) * 4;
            g_xT[t0][e][b] = v.x; g_xT[t0][e + 1][b] = v.y;
            g_xT[t0][e + 2][b] = v.z; g_xT[t0][e + 3][b] = v.w;
        }
    }

    // ---- stage this CTA's weight slice into smem (once) ----
    // row rho = g*4 + r  ->  global gate-row (cta*4+g) + 512*r
    // wA row: [0..1023] = w_ih0 row, [1024..1535] = w_hh0 row
    for (int i = tid; i < 16 * 256; i += NTHR) {        // w_ih0: 16 rows x 256 f4
        int rho = i >> 8, col = i & 255;
        int grow = (cta * 4 + (rho >> 2)) + 512 * (rho & 3);
        *(float4*)(wA + rho * WA_STR + col * 4) =
            __ldg((const float4*)(w_ih0 + (size_t)grow * 1024) + col);
    }
    for (int i = tid; i < 16 * 128; i += NTHR) {        // w_hh0: 16 rows x 128 f4
        int rho = i >> 7, col = i & 127;
        int grow = (cta * 4 + (rho >> 2)) + 512 * (rho & 3);
        *(float4*)(wA + rho * WA_STR + 1024 + col * 4) =
            __ldg((const float4*)(w_hh0 + (size_t)grow * 512) + col);
    }
    for (int i = tid; i < 16 * 128; i += NTHR) {        // w_ih1
        int rho = i >> 7, col = i & 127;
        int grow = (cta * 4 + (rho >> 2)) + 512 * (rho & 3);
        *(float4*)(wB + rho * WB_STR + col * 4) =
            __ldg((const float4*)(w_ih1 + (size_t)grow * 512) + col);
    }
    for (int i = tid; i < 16 * 128; i += NTHR) {        // w_hh1
        int rho = i >> 7, col = i & 127;
        int grow = (cta * 4 + (rho >> 2)) + 512 * (rho & 3);
        *(float4*)(wB + rho * WB_STR + 512 + col * 4) =
            __ldg((const float4*)(w_hh1 + (size_t)grow * 512) + col);
    }
    for (int i = tid; i < 4 * 256; i += NTHR) {         // attn_out_w: 4 rows x 256 f4
        int rr = i >> 8, col = i & 255;
        *(float4*)(wE + rr * WE_STR + col * 4) =
            __ldg((const float4*)(attn_out_w + (size_t)(cta * 4 + rr) * 1024) + col);
    }
    gbar();

    // warp roles: g = row-group, kq = K-quarter; lane: r = gate/seg, q = batch-quad
    const int g = warp >> 2, kq = warp & 3;
    const int r = lane >> 3, q = lane & 7;
    const int rho = g * 4 + r;
    const float* wAp = wA + rho * WA_STR;
    const float* wBp = wB + rho * WB_STR;

    float c0r = 0.f, c1r = 0.f;
    float biA[4], biB[4];
    if (tid < 128) {
        int jj = tid >> 5, ju = cta * 4 + jj;
#pragma unroll
        for (int rr = 0; rr < 4; rr++) {
            biA[rr] = __ldg(b_ih0 + ju + 512 * rr) + __ldg(b_hh0 + ju + 512 * rr);
            biB[rr] = __ldg(b_ih1 + ju + 512 * rr) + __ldg(b_hh1 + ju + 512 * rr);
        }
    }

    for (int t = 0; t < Tn; t++) {
        const int cur = t & 1, prv = cur ^ 1;

        // ---------- Phase A: LSTM layer 0 gates (K = x512|feed512|h0 512, kq-split) ----------
        {
            unsigned long long A0 = 0ull, A1 = 0ull;
            const int ko = kq * 128;
            mvseg(wAp + ko,        &g_xT[t][ko][0],    128, q, A0, A1);
            mvseg(wAp + 512 + ko,  &g_feedT[ko][0],    128, q, A0, A1);
            mvseg(wAp + 1024 + ko, &g_h0T[prv][ko][0], 128, q, A0, A1);
            float2 v0 = unpack2(A0), v1 = unpack2(A1);
            *(float4*)&sA[kq][g][r][q * 4] = make_float4(v0.x, v0.y, v1.x, v1.y);
            __syncthreads();
            if (tid < 128) {
                int b = tid & 31, jj = tid >> 5;
                float gi = sA[0][jj][0][b] + sA[1][jj][0][b] + sA[2][jj][0][b] + sA[3][jj][0][b] + biA[0];
                float gf = sA[0][jj][1][b] + sA[1][jj][1][b] + sA[2][jj][1][b] + sA[3][jj][1][b] + biA[1];
                float gg = sA[0][jj][2][b] + sA[1][jj][2][b] + sA[2][jj][2][b] + sA[3][jj][2][b] + biA[2];
                float go = sA[0][jj][3][b] + sA[1][jj][3][b] + sA[2][jj][3][b] + sA[3][jj][3][b] + biA[3];
                c0r = sigm(gf) * c0r + sigm(gi) * tanhf(gg);
                g_h0T[cur][cta * 4 + jj][b] = sigm(go) * tanhf(c0r);
            }
        }
        gbar();

        // ---------- Phase B: LSTM layer 1 gates (K = h0cur 512 | h1prv 512) ----------
        {
            unsigned long long A0 = 0ull, A1 = 0ull;
            const int ko = kq * 128;
            mvseg(wBp + ko,       &g_h0T[cur][ko][0], 128, q, A0, A1);
            mvseg(wBp + 512 + ko, &g_h1T[prv][ko][0], 128, q, A0, A1);
            float2 v0 = unpack2(A0), v1 = unpack2(A1);
            *(float4*)&sA[kq][g][r][q * 4] = make_float4(v0.x, v0.y, v1.x, v1.y);
            __syncthreads();
            if (tid < 128) {
                int b = tid & 31, jj = tid >> 5;
                float gi = sA[0][jj][0][b] + sA[1][jj][0][b] + sA[2][jj][0][b] + sA[3][jj][0][b] + biB[0];
                float gf = sA[0][jj][1][b] + sA[1][jj][1][b] + sA[2][jj][1][b] + sA[3][jj][1][b] + biB[1];
                float gg = sA[0][jj][2][b] + sA[1][jj][2][b] + sA[2][jj][2][b] + sA[3][jj][2][b] + biB[2];
                float go = sA[0][jj][3][b] + sA[1][jj][3][b] + sA[2][jj][3][b] + sA[3][jj][3][b] + biB[3];
                c1r = sigm(gf) * c1r + sigm(gi) * tanhf(gg);
                g_h1T[cur][cta * 4 + jj][b] = sigm(go) * tanhf(c1r);
            }
        }
        gbar();

        // ---------- Phase D: scores (encq·h1) -> softmax -> ctx (one CTA per batch) ----------
        if (cta < Bn) {
            const int b = cta;
            s_q[tid] = __ldca(&g_h1T[cur][tid][b]);
            __syncthreads();
#pragma unroll
            for (int i = 0; i < 8; i++) {
                int sp = warp * 8 + i;
                const float4* er = (const float4*)(g_encq[(size_t)b * Sn + sp]);
                const float4* qr = (const float4*)s_q;
                float acc = 0.f;
#pragma unroll
                for (int c4 = 0; c4 < 4; c4++) {
                    float4 e = __ldca(er + c4 * 32 + lane);
                    float4 q4 = qr[c4 * 32 + lane];
                    acc += e.x * q4.x + e.y * q4.y + e.z * q4.z + e.w * q4.w;
                }
#pragma unroll
                for (int o = 16; o; o >>= 1) acc += __shfl_xor_sync(~0u, acc, o);
                if (lane == 0)
                    s_sc[sp] = (__ldg(mask + b * Sn + sp) == 0) ? NEGV : acc;
            }
            __syncthreads();
            float mv = (tid < 128) ? s_sc[tid] : -3e38f;
#pragma unroll
            for (int o = 16; o; o >>= 1) mv = fmaxf(mv, __shfl_xor_sync(~0u, mv, o));
            if (tid < 128 && lane == 0) s_red[warp] = mv;
            __syncthreads();
            if (tid == 0) {
                float m = s_red[0];
                for (int w = 1; w < 4; w++) m = fmaxf(m, s_red[w]);
                s_red[16] = m;
            }
            __syncthreads();
            float ev = 0.f;
            if (tid < 128) ev = __expf(s_sc[tid] - s_red[16]);
            float sv = ev;
#pragma unroll
            for (int o = 16; o; o >>= 1) sv += __shfl_xor_sync(~0u, sv, o);
            if (tid < 128 && lane == 0) s_red[warp] = sv;
            __syncthreads();
            if (tid == 0) {
                float s = 0.f;
                for (int w = 0; w < 4; w++) s += s_red[w];
                s_red[17] = 1.f / s;
            }
            __syncthreads();
            if (tid < 128) s_sc[tid] = ev * s_red[17];
            __syncthreads();
            {
                int h = tid;
                const float* ep = enc + (size_t)b * Sn * Hn + h;
                float a0 = 0.f, a1 = 0.f, a2 = 0.f, a3 = 0.f;
#pragma unroll 8
                for (int s = 0; s < 32; s++) {
                    a0 += s_sc[s]      * __ldg(ep + s * Hn);
                    a1 += s_sc[s + 32] * __ldg(ep + (s + 32) * Hn);
                    a2 += s_sc[s + 64] * __ldg(ep + (s + 64) * Hn);
                    a3 += s_sc[s + 96] * __ldg(ep + (s + 96) * Hn);
                }
                g_ctxT[h][b] = (a0 + a1) + (a2 + a3);
            }
        }
        gbar();

        // ---------- Phase E: input_feed = tanh(attn_out_w @ [ctx512; h1cur512]) ----------
        {
            unsigned long long A0 = 0ull, A1 = 0ull;
            const int seg = kq * 4 + r;   // 16 segments of 64
            const float* src = (seg < 8) ? &g_ctxT[seg * 64][0]
                                         : &g_h1T[cur][(seg - 8) * 64][0];
            mvseg(wE + g * WE_STR + seg * 64, src, 64, q, A0, A1);
            float2 v0 = unpack2(A0), v1 = unpack2(A1);
            *(float4*)&sA[kq][g][r][q * 4] = make_float4(v0.x, v0.y, v1.x, v1.y);
            __syncthreads();
            if (tid < 128) {
                int b = tid & 31, jj = tid >> 5;
                float s = 0.f;
#pragma unroll
                for (int kk = 0; kk < 4; kk++)
#pragma unroll
                    for (int rr = 0; rr < 4; rr++) s += sA[kk][jj][rr][b];
                float f = tanhf(s);
                g_feedT[cta * 4 + jj][b] = f;
                g_dec[b * Tn + t][cta * 4 + jj] = f;
            }
        }
        gbar();
    }
}

// ---------------- 512x512 transpose (attn_in_w -> g_attT) ----------------
__global__ void __launch_bounds__(256)
trans512(const float* __restrict__ src, float* __restrict__ dst)
{
    __shared__ float tile[32][33];
    int bx = blockIdx.x * 32, by = blockIdx.y * 32;
    int tx = threadIdx.x & 31, ty = threadIdx.x >> 5;   // 32x8
#pragma unroll
    for (int i = 0; i < 4; i++)
        tile[ty + i * 8][tx] = __ldg(src + (size_t)(by + ty + i * 8) * 512 + bx + tx);
    __syncthreads();
#pragma unroll
    for (int i = 0; i < 4; i++)
        dst[(size_t)(bx + ty + i * 8) * 512 + by + tx] = tile[tx][ty + i * 8];
}

// ---------------- SIMT f32x2 gemm: C = A @ W^T (+bias), fp32 out ----------------
__global__ void __launch_bounds__(256)
gemm_nt(const float* __restrict__ A, const float* __restrict__ W,
        const float* __restrict__ bias, float* __restrict__ C,
        int M, int N, int K)
{
    __shared__ __align__(16) float As[16][128];
    __shared__ __align__(16) float Ws[16][128];
    const int m0 = blockIdx.y * 128, n0 = blockIdx.x * 128;
    const int tid = threadIdx.x;
    const int tx = tid & 15, ty = tid >> 4;
    const int lrow = tid >> 1, lcol = (tid & 1) * 8;

    unsigned long long acc2[8][4];
#pragma unroll
    for (int i = 0; i < 8; i++)
#pragma unroll
        for (int jj = 0; jj < 4; jj++) acc2[i][jj] = 0ull;

    const float* Aload = A + (size_t)(m0 + lrow) * K + lcol;
    const float* Wload = W + (size_t)(n0 + lrow) * K + lcol;

    for (int k0 = 0; k0 < K; k0 += 16) {
        float4 a0 = __ldg((const float4*)(Aload + k0));
        float4 a1 = __ldg((const float4*)(Aload + k0 + 4));
        float4 w0 = __ldg((const float4*)(Wload + k0));
        float4 w1 = __ldg((const float4*)(Wload + k0 + 4));
        __syncthreads();
        As[lcol + 0][lrow] = a0.x; As[lcol + 1][lrow] = a0.y;
        As[lcol + 2][lrow] = a0.z; As[lcol + 3][lrow] = a0.w;
        As[lcol + 4][lrow] = a1.x; As[lcol + 5][lrow] = a1.y;
        As[lcol + 6][lrow] = a1.z; As[lcol + 7][lrow] = a1.w;
        Ws[lcol + 0][lrow] = w0.x; Ws[lcol + 1][lrow] = w0.y;
        Ws[lcol + 2][lrow] = w0.z; Ws[lcol + 3][lrow] = w0.w;
        Ws[lcol + 4][lrow] = w1.x; Ws[lcol + 5][lrow] = w1.y;
        Ws[lcol + 6][lrow] = w1.z; Ws[lcol + 7][lrow] = w1.w;
        __syncthreads();
#pragma unroll
        for (int kk = 0; kk < 16; kk++) {
            float4 av0 = *(const float4*)&As[kk][ty * 8];
            float4 av1 = *(const float4*)&As[kk][ty * 8 + 4];
            const ulonglong2* wp = (const ulonglong2*)&Ws[kk][tx * 8];
            ulonglong2 b01 = wp[0], b23 = wp[1];
            float a8[8] = {av0.x, av0.y, av0.z, av0.w, av1.x, av1.y, av1.z, av1.w};
#pragma unroll
            for (int i = 0; i < 8; i++) {
                unsigned long long a2 = pack2(a8[i]);
                ffma2(acc2[i][0], a2, b01.x);
                ffma2(acc2[i][1], a2, b01.y);
                ffma2(acc2[i][2], a2, b23.x);
                ffma2(acc2[i][3], a2, b23.y);
            }
        }
    }
#pragma unroll
    for (int i = 0; i < 8; i++) {
        float* Crow = C + (size_t)(m0 + ty * 8 + i) * N + n0 + tx * 8;
#pragma unroll
        for (int jj = 0; jj < 4; jj++) {
            float2 v = unpack2(acc2[i][jj]);
            if (bias) {
                v.x += __ldg(bias + n0 + tx * 8 + 2 * jj);
                v.y += __ldg(bias + n0 + tx * 8 + 2 * jj + 1);
            }
            *(float2*)(Crow + 2 * jj) = v;
        }
    }
}

// ---------------- SIMT f32x2 gemm (out_proj) -> bf16 hi/lo ----------------
__device__ __forceinline__ void split_bf16(float v, __nv_bfloat16& h, __nv_bfloat16& l)
{
    h = __float2bfloat16(v);
    l = __float2bfloat16(v - __bfloat162float(h));
}

__global__ void __launch_bounds__(256)
gemm_nt_split(const float* __restrict__ A, const float* __restrict__ W,
              const float* __restrict__ bias,
              __nv_bfloat16* __restrict__ Chi, __nv_bfloat16* __restrict__ Clo,
              int M, int N, int K)
{
    __shared__ __align__(16) float As[16][128];
    __shared__ __align__(16) float Ws[16][128];
    const int m0 = blockIdx.y * 128, n0 = blockIdx.x * 128;
    const int tid = threadIdx.x;
    const int tx = tid & 15, ty = tid >> 4;
    const int lrow = tid >> 1, lcol = (tid & 1) * 8;

    unsigned long long acc2[8][4];
#pragma unroll
    for (int i = 0; i < 8; i++)
#pragma unroll
        for (int jj = 0; jj < 4; jj++) acc2[i][jj] = 0ull;

    const float* Aload = A + (size_t)(m0 + lrow) * K + lcol;
    const float* Wload = W + (size_t)(n0 + lrow) * K + lcol;

    for (int k0 = 0; k0 < K; k0 += 16) {
        float4 a0 = __ldg((const float4*)(Aload + k0));
        float4 a1 = __ldg((const float4*)(Aload + k0 + 4));
        float4 w0 = __ldg((const float4*)(Wload + k0));
        float4 w1 = __ldg((const float4*)(Wload + k0 + 4));
        __syncthreads();
        As[lcol + 0][lrow] = a0.x; As[lcol + 1][lrow] = a0.y;
        As[lcol + 2][lrow] = a0.z; As[lcol + 3][lrow] = a0.w;
        As[lcol + 4][lrow] = a1.x; As[lcol + 5][lrow] = a1.y;
        As[lcol + 6][lrow] = a1.z; As[lcol + 7][lrow] = a1.w;
        Ws[lcol + 0][lrow] = w0.x; Ws[lcol + 1][lrow] = w0.y;
        Ws[lcol + 2][lrow] = w0.z; Ws[lcol + 3][lrow] = w0.w;
        Ws[lcol + 4][lrow] = w1.x; Ws[lcol + 5][lrow] = w1.y;
        Ws[lcol + 6][lrow] = w1.z; Ws[lcol + 7][lrow] = w1.w;
        __syncthreads();
#pragma unroll
        for (int kk = 0; kk < 16; kk++) {
            float4 av0 = *(const float4*)&As[kk][ty * 8];
            float4 av1 = *(const float4*)&As[kk][ty * 8 + 4];
            const ulonglong2* wp = (const ulonglong2*)&Ws[kk][tx * 8];
            ulonglong2 b01 = wp[0], b23 = wp[1];
            float a8[8] = {av0.x, av0.y, av0.z, av0.w, av1.x, av1.y, av1.z, av1.w};
#pragma unroll
            for (int i = 0; i < 8; i++) {
                unsigned long long a2 = pack2(a8[i]);
                ffma2(acc2[i][0], a2, b01.x);
                ffma2(acc2[i][1], a2, b01.y);
                ffma2(acc2[i][2], a2, b23.x);
                ffma2(acc2[i][3], a2, b23.y);
            }
        }
    }
#pragma unroll
    for (int i = 0; i < 8; i++) {
        size_t rowoff = (size_t)(m0 + ty * 8 + i) * N + n0 + tx * 8;
        unsigned short tmph[8], tmpl[8];
#pragma unroll
        for (int jj = 0; jj < 4; jj++) {
            float2 v = unpack2(acc2[i][jj]);
            v.x += __ldg(bias + n0 + tx * 8 + 2 * jj);
            v.y += __ldg(bias + n0 + tx * 8 + 2 * jj + 1);
            __nv_bfloat16 h0, l0, h1, l1;
            split_bf16(v.x, h0, l0);
            split_bf16(v.y, h1, l1);
            tmph[2 * jj] = __bfloat16_as_ushort(h0); tmph[2 * jj + 1] = __bfloat16_as_ushort(h1);
            tmpl[2 * jj] = __bfloat16_as_ushort(l0); tmpl[2 * jj + 1] = __bfloat16_as_ushort(l1);
        }
        uint2 H, L, H2, L2;
        H.x = (uint32_t)tmph[0] | ((uint32_t)tmph[1] << 16);
        H.y = (uint32_t)tmph[2] | ((uint32_t)tmph[3] << 16);
        L.x = (uint32_t)tmpl[0] | ((uint32_t)tmpl[1] << 16);
        L.y = (uint32_t)tmpl[2] | ((uint32_t)tmpl[3] << 16);
        H2.x = (uint32_t)tmph[4] | ((uint32_t)tmph[5] << 16);
        H2.y = (uint32_t)tmph[6] | ((uint32_t)tmph[7] << 16);
        L2.x = (uint32_t)tmpl[4] | ((uint32_t)tmpl[5] << 16);
        L2.y = (uint32_t)tmpl[6] | ((uint32_t)tmpl[7] << 16);
        *(uint2*)(Chi + rowoff) = H;  *(uint2*)(Chi + rowoff + 4) = H2;
        *(uint2*)(Clo + rowoff) = L;  *(uint2*)(Clo + rowoff + 4) = L2;
    }
}

// ---------------- fp32 -> bf16 hi/lo split (embed) ----------------
__global__ void __launch_bounds__(256)
conv_split(const float4* __restrict__ src, uint2* __restrict__ hi, uint2* __restrict__ lo)
{
    int i = blockIdx.x * 256 + threadIdx.x;
    float4 v = __ldg(src + i);
    __nv_bfloat16 h0, l0, h1, l1, h2, l2, h3, l3;
    split_bf16(v.x, h0, l0); split_bf16(v.y, h1, l1);
    split_bf16(v.z, h2, l2); split_bf16(v.w, h3, l3);
    uint2 H, L;
    H.x = (uint32_t)__bfloat16_as_ushort(h0) | ((uint32_t)__bfloat16_as_ushort(h1) << 16);
    H.y = (uint32_t)__bfloat16_as_ushort(h2) | ((uint32_t)__bfloat16_as_ushort(h3) << 16);
    L.x = (uint32_t)__bfloat16_as_ushort(l0) | ((uint32_t)__bfloat16_as_ushort(l1) << 16);
    L.y = (uint32_t)__bfloat16_as_ushort(l2) | ((uint32_t)__bfloat16_as_ushort(l3) << 16);
    hi[i] = H; lo[i] = L;
}

// ---------------- mma.sync bf16 3-pass GEMM: C = A @ B^T ----------------
static constexpr int KC = 32;
static constexpr int NCHUNK = En / KC;
static constexpr int ROWB = 80;
static constexpr int MATB = 128 * ROWB;
static constexpr int STAGEB = 4 * MATB;
static constexpr int GSMEM2 = 2 * STAGEB;

__device__ __forceinline__ void ldmA(uint32_t* r, uint32_t addr)
{
    asm volatile("ldmatrix.sync.aligned.m8n8.x4.shared.b16 {%0,%1,%2,%3}, [%4];"
                 : "=r"(r[0]), "=r"(r[1]), "=r"(r[2]), "=r"(r[3]) : "r"(addr));
}
__device__ __forceinline__ void ldmB(uint32_t* r, uint32_t addr)
{
    asm volatile("ldmatrix.sync.aligned.m8n8.x2.shared.b16 {%0,%1}, [%2];"
                 : "=r"(r[0]), "=r"(r[1]) : "r"(addr));
}
__device__ __forceinline__ void mma16816(float* d, const uint32_t* a, const uint32_t* b)
{
    asm volatile("mma.sync.aligned.m16n8k16.row.col.f32.bf16.bf16.f32 "
                 "{%0,%1,%2,%3}, {%4,%5,%6,%7}, {%8,%9}, {%0,%1,%2,%3};"
                 : "+f"(d[0]), "+f"(d[1]), "+f"(d[2]), "+f"(d[3])
                 : "r"(a[0]), "r"(a[1]), "r"(a[2]), "r"(a[3]), "r"(b[0]), "r"(b[1]));
}

__global__ void __launch_bounds__(256, 2)
gemm_bf16(const __nv_bfloat16* __restrict__ Ahi, const __nv_bfloat16* __restrict__ Alo,
          const __nv_bfloat16* __restrict__ Bhi, const __nv_bfloat16* __restrict__ Blo,
          float* __restrict__ C, int N, int K)
{
    extern __shared__ char smem[];
    const uint32_t su = s2u(smem);
    const int tid = threadIdx.x, wid = tid >> 5, lane = tid & 31;
    const int m0 = blockIdx.x * 128, n0 = blockIdx.y * 128;
    const int wm = wid & 1, wn = wid >> 1;

    const int ci0 = tid;
    auto load_stage = [&](int chunk) {
        const uint32_t sb = su + (chunk & 1) * STAGEB;
#pragma unroll
        for (int r8 = 0; r8 < 8; r8++) {
            int ci = ci0 + r8 * 256;
            int mat = ci >> 9, rem = ci & 511;
            int row = rem >> 2, seg = rem & 3;
            const __nv_bfloat16* g;
            if (mat == 0)      g = Ahi + (size_t)(m0 + row) * K + chunk * KC + seg * 8;
            else if (mat == 1) g = Alo + (size_t)(m0 + row) * K + chunk * KC + seg * 8;
            else if (mat == 2) g = Bhi + (size_t)(n0 + row) * K + chunk * KC + seg * 8;
            else               g = Blo + (size_t)(n0 + row) * K + chunk * KC + seg * 8;
            cp16(sb + mat * MATB + row * ROWB + seg * 16, g);
        }
        asm volatile("cp.async.commit_group;" ::: "memory");
    };

    float acc[4][4][4];
#pragma unroll
    for (int i = 0; i < 4; i++)
#pragma unroll
        for (int jj = 0; jj < 4; jj++)
#pragma unroll
            for (int k = 0; k < 4; k++) acc[i][jj][k] = 0.f;

    load_stage(0);
    load_stage(1);

    for (int c = 0; c < NCHUNK; c++) {
        if (c < NCHUNK - 1) asm volatile("cp.async.wait_group 1;" ::: "memory");
        else                asm volatile("cp.async.wait_group 0;" ::: "memory");
        __syncthreads();
        const uint32_t sb = su + (c & 1) * STAGEB;
        const uint32_t aHiB = sb,            aLoB = sb + MATB;
        const uint32_t bHiB = sb + 2 * MATB, bLoB = sb + 3 * MATB;
#pragma unroll
        for (int ks = 0; ks < 2; ks++) {
            const uint32_t aoff = (uint32_t)((wm * 64 + (lane & 15)) * ROWB
                                             + (ks * 16 + (lane >> 4) * 8) * 2);
            const int l = lane & 15;
            const uint32_t boff = (uint32_t)((wn * 32 + (l & 7)) * ROWB
                                             + (ks * 16 + (l >> 3) * 8) * 2);
            uint32_t ah[4][4], al[4][4], bh[4][2], bl[4][2];
#pragma unroll
            for (int mi = 0; mi < 4; mi++) {
                ldmA(ah[mi], aHiB + aoff + mi * 16 * ROWB);
                ldmA(al[mi], aLoB + aoff + mi * 16 * ROWB);
            }
#pragma unroll
            for (int ni = 0; ni < 4; ni++) {
                ldmB(bh[ni], bHiB + boff + ni * 8 * ROWB);
                ldmB(bl[ni], bLoB + boff + ni * 8 * ROWB);
            }
#pragma unroll
            for (int mi = 0; mi < 4; mi++)
#pragma unroll
                for (int ni = 0; ni < 4; ni++) {
                    mma16816(acc[mi][ni], ah[mi], bh[ni]);
                    mma16816(acc[mi][ni], ah[mi], bl[ni]);
                    mma16816(acc[mi][ni], al[mi], bh[ni]);
                }
        }
        __syncthreads();
        if (c + 2 < NCHUNK) load_stage(c + 2);
    }

    const int mbase = m0 + wm * 64 + (lane >> 2);
    const int nbase = n0 + wn * 32 + (lane & 3) * 2;
#pragma unroll
    for (int mi = 0; mi < 4; mi++)
#pragma unroll
        for (int ni = 0; ni < 4; ni++) {
            float* p0 = C + (size_t)(mbase + mi * 16) * N + nbase + ni * 8;
            float* p1 = C + (size_t)(mbase + mi * 16 + 8) * N + nbase + ni * 8;
            *(float2*)p0 = make_float2(acc[mi][ni][0], acc[mi][ni][1]);
            *(float2*)p1 = make_float2(acc[mi][ni][2], acc[mi][ni][3]);
        }
}

extern "C" void kernel_launch(void* const* d_in, const int* in_sizes, int n_in,
                              void* d_out, int out_size)
{
    const int*   tokens     = (const int*)d_in[0];
    const float* enc        = (const float*)d_in[1];
    const int*   mask       = (const int*)d_in[2];
    const float* embed      = (const float*)d_in[3];
    const float* w_ih0      = (const float*)d_in[4];
    const float* w_hh0      = (const float*)d_in[5];
    const float* b_ih0      = (const float*)d_in[6];
    const float* b_hh0      = (const float*)d_in[7];
    const float* w_ih1      = (const float*)d_in[8];
    const float* w_hh1      = (const float*)d_in[9];
    const float* b_ih1      = (const float*)d_in[10];
    const float* b_hh1      = (const float*)d_in[11];
    const float* attn_in_w  = (const float*)d_in[12];
    const float* attn_out_w = (const float*)d_in[13];
    const float* out_proj_w = (const float*)d_in[14];
    const float* out_proj_b = (const float*)d_in[15];
    float* out = (float*)d_out;

    float *dec, *encq, *attT;
    __nv_bfloat16 *Ahi, *Alo, *Bhi, *Blo;
    cudaGetSymbolAddress((void**)&dec, g_dec);
    cudaGetSymbolAddress((void**)&encq, g_encq);
    cudaGetSymbolAddress((void**)&attT, g_attT);
    cudaGetSymbolAddress((void**)&Ahi, g_Ahi);
    cudaGetSymbolAddress((void**)&Alo, g_Alo);
    cudaGetSymbolAddress((void**)&Bhi, g_Bhi);
    cudaGetSymbolAddress((void**)&Blo, g_Blo);

    cudaFuncSetAttribute(gemm_bf16, cudaFuncAttributeMaxDynamicSharedMemorySize, GSMEM2);
    cudaFuncSetAttribute(recurrent_kernel, cudaFuncAttributeMaxDynamicSharedMemorySize, DSMEM);

    static cudaStream_t s2 = nullptr;
    static cudaEvent_t evA = nullptr, evB = nullptr;
    if (!s2) {
        cudaStreamCreateWithFlags(&s2, cudaStreamNonBlocking);
        cudaEventCreateWithFlags(&evA, cudaEventDisableTiming);
        cudaEventCreateWithFlags(&evB, cudaEventDisableTiming);
    }

    // side stream: embed hi/lo conversion (independent; overlaps recurrence)
    cudaEventRecord(evA, 0);
    cudaStreamWaitEvent(s2, evA, 0);
    conv_split<<<Vn * En / 1024, 256, 0, s2>>>((const float4*)embed, (uint2*)Bhi, (uint2*)Blo);
    cudaEventRecord(evB, s2);

    // encq = enc @ attn_in_w (via transpose + gemm_nt) — replaces phase C
    trans512<<<dim3(16, 16), 256>>>(attn_in_w, attT);
    gemm_nt<<<dim3(Hn / 128, (Bn * Sn) / 128), 256>>>(enc, attT, nullptr, encq,
                                                      Bn * Sn, Hn, Hn);
    recurrent_kernel<<<NCTA, NTHR, DSMEM>>>(tokens, enc, mask, embed,
                                            w_ih0, w_hh0, b_ih0, b_hh0,
                                            w_ih1, w_hh1, b_ih1, b_hh1,
                                            attn_out_w);
    gemm_nt_split<<<dim3(En / 128, (Bn * Tn) / 128), 256>>>(dec, out_proj_w, out_proj_b,
                                                            Ahi, Alo, Bn * Tn, En, Hn);
    cudaStreamWaitEvent(0, evB, 0);
    gemm_bf16<<<dim3((Bn * Tn) / 128, Vn / 128), 256, GSMEM2>>>(Ahi, Alo, Bhi, Blo, out, Vn, En);
}

// round 11
// speedup vs baseline: 1.4376x; 1.0831x over previous
#include <cuda_runtime.h>
#include <cuda_bf16.h>
#include <cstdint>

#define NCTA 128
#define NTHR 512
static constexpr int Bn = 32, Tn = 64, Sn = 128, Hn = 512, En = 512, Vn = 32000;
static constexpr float NEGV = -1e4f;

// ---------------- device scratch (allocation-free) ----------------
__device__ __align__(16) float g_x[Bn * Tn][En];      // gathered embeddings, row = t*Bn+b
__device__ __align__(16) float g_xw[Bn * Tn * 2048];  // x @ w_ih0[:, :512]^T
__device__ __align__(16) float g_feedT[Hn][Bn];
__device__ __align__(16) float g_h0T[2][Hn][Bn];
__device__ __align__(16) float g_h1T[2][Hn][Bn];
__device__ __align__(16) float g_ctxT[Hn][Bn];
__device__ __align__(16) float g_dec[Bn * Tn][Hn];
__device__ __align__(16) float g_encq[Bn * Sn][Hn];   // enc @ attn_in_w
__device__ __align__(16) float g_attT[Hn * Hn];       // attn_in_w transposed
__device__ __nv_bfloat16 g_Ahi[Bn * Tn * En];
__device__ __nv_bfloat16 g_Alo[Bn * Tn * En];
__device__ __nv_bfloat16 g_Bhi[Vn * En];
__device__ __nv_bfloat16 g_Blo[Vn * En];
__device__ unsigned g_count;
__device__ volatile unsigned g_gen;

// ---------------- small helpers ----------------
__device__ __forceinline__ uint32_t s2u(const void* p)
{
    uint32_t a;
    asm("{ .reg .u64 t; cvta.to.shared.u64 t, %1; cvt.u32.u64 %0, t; }" : "=r"(a) : "l"(p));
    return a;
}
__device__ __forceinline__ void cp16(uint32_t s, const void* g)
{
    asm volatile("cp.async.cg.shared.global [%0], [%1], 16;" :: "r"(s), "l"(g) : "memory");
}
__device__ __forceinline__ float sigm(float x) { return 1.f / (1.f + __expf(-x)); }

__device__ __forceinline__ unsigned long long pack2(float x)
{ unsigned long long r; asm("mov.b64 %0, {%1, %1};" : "=l"(r) : "f"(x)); return r; }
__device__ __forceinline__ void ffma2(unsigned long long& d, unsigned long long a, unsigned long long b)
{ asm("fma.rn.f32x2 %0, %1, %2, %0;" : "+l"(d) : "l"(a), "l"(b)); }
__device__ __forceinline__ float2 unpack2(unsigned long long v)
{ float2 r; asm("mov.b64 {%0, %1}, %2;" : "=f"(r.x), "=f"(r.y) : "l"(v)); return r; }

// matvec segment: weight row from SMEM (LDS) vs transposed activations in L2 [k][32]
__device__ __forceinline__ void mvseg(const float* __restrict__ wrow,   // smem
                                      const float* __restrict__ act,    // global
                                      int klen, int q,
                                      unsigned long long& A0, unsigned long long& A1)
{
    const char* ap = (const char*)(act + q * 4);
#pragma unroll 4
    for (int k0 = 0; k0 < klen; k0 += 8) {
        float4 w0 = *(const float4*)(wrow + k0);
        float4 w1 = *(const float4*)(wrow + k0 + 4);
        ulonglong2 av[8];
#pragma unroll
        for (int kk = 0; kk < 8; kk++)
            av[kk] = __ldca((const ulonglong2*)(ap + (size_t)(k0 + kk) * 128));
        float ws[8] = {w0.x, w0.y, w0.z, w0.w, w1.x, w1.y, w1.z, w1.w};
#pragma unroll
        for (int kk = 0; kk < 8; kk++) {
            unsigned long long wp = pack2(ws[kk]);
            ffma2(A0, wp, av[kk].x);
            ffma2(A1, wp, av[kk].y);
        }
    }
}

// ---------------- grid barrier (all 128 CTAs co-resident) ----------------
__device__ __forceinline__ void gbar()
{
    __threadfence();
    __syncthreads();
    if (threadIdx.x == 0) {
        unsigned g = g_gen;
        unsigned a = atomicAdd(&g_count, 1u);
        if (a == NCTA - 1u) {
            g_count = 0u;
            __threadfence();
            g_gen = g + 1u;
        } else {
            while (g_gen == g) { }
        }
    }
    __syncthreads();
    __threadfence();
}

// dynamic smem layout for recurrent kernel (weight slices, padded rows)
static constexpr int WA_STR = 1540;   // 1536 + 4 pad
static constexpr int WB_STR = 1028;   // 1024 + 4 pad
static constexpr int WE_STR = 1028;
static constexpr int OFF_WA = 0;
static constexpr int OFF_WB = OFF_WA + 16 * WA_STR;   // floats
static constexpr int OFF_WE = OFF_WB + 16 * WB_STR;
static constexpr int DSMEM = (OFF_WE + 4 * WE_STR) * 4;   // bytes = 180800

// ---------------- embed gather: g_x[t*Bn+b] = embed[tokens[b][t]] ----------------
__global__ void __launch_bounds__(256)
gather_x(const int* __restrict__ tokens, const float* __restrict__ embed)
{
    int p = blockIdx.x * 8 + (threadIdx.x >> 5);  // 0..2047 = t*32+b
    int lane = threadIdx.x & 31;
    int t = p >> 5, b = p & 31;
    int tok = __ldg(tokens + b * Tn + t);
    const float4* er = (const float4*)(embed + (size_t)tok * En);
    float4* dr = (float4*)g_x[t * Bn + b];
#pragma unroll
    for (int i = 0; i < 4; i++)
        dr[i * 32 + lane] = __ldg(er + i * 32 + lane);
}

// ---------------- persistent recurrence (512 threads: 16 warps) ----------------
__global__ void __launch_bounds__(NTHR, 1)
recurrent_kernel(const float* __restrict__ enc,
                 const int* __restrict__ mask,
                 const float* __restrict__ w_ih0, const float* __restrict__ w_hh0,
                 const float* __restrict__ b_ih0, const float* __restrict__ b_hh0,
                 const float* __restrict__ w_ih1, const float* __restrict__ w_hh1,
                 const float* __restrict__ b_ih1, const float* __restrict__ b_hh1,
                 const float* __restrict__ attn_out_w)
{
    extern __shared__ __align__(16) float wsm[];
    float* wA = wsm + OFF_WA;
    float* wB = wsm + OFF_WB;
    float* wE = wsm + OFF_WE;

    const int tid = threadIdx.x, cta = blockIdx.x;
    const int warp = tid >> 5, lane = tid & 31;
    const int gtid = cta * NTHR + tid;

    __shared__ __align__(16) float sA[4][4][4][32];   // [kq][g][r][batch]; also reused as [4][128]
    __shared__ __align__(16) float s_q[512];
    __shared__ float s_sc[128];
    __shared__ float s_red[32];

    // ---- init recurrent state ----
    for (int i = gtid; i < Hn * Bn; i += NCTA * NTHR) {
        (&g_feedT[0][0])[i] = 0.f;
        (&g_h0T[0][0][0])[i] = 0.f; (&g_h0T[1][0][0])[i] = 0.f;
        (&g_h1T[0][0][0])[i] = 0.f; (&g_h1T[1][0][0])[i] = 0.f;
    }

    // ---- stage this CTA's weight slice into smem (once) ----
    for (int i = tid; i < 16 * 256; i += NTHR) {        // w_ih0: 16 rows x 256 f4
        int rho = i >> 8, col = i & 255;
        int grow = (cta * 4 + (rho >> 2)) + 512 * (rho & 3);
        *(float4*)(wA + rho * WA_STR + col * 4) =
            __ldg((const float4*)(w_ih0 + (size_t)grow * 1024) + col);
    }
    for (int i = tid; i < 16 * 128; i += NTHR) {        // w_hh0
        int rho = i >> 7, col = i & 127;
        int grow = (cta * 4 + (rho >> 2)) + 512 * (rho & 3);
        *(float4*)(wA + rho * WA_STR + 1024 + col * 4) =
            __ldg((const float4*)(w_hh0 + (size_t)grow * 512) + col);
    }
    for (int i = tid; i < 16 * 128; i += NTHR) {        // w_ih1
        int rho = i >> 7, col = i & 127;
        int grow = (cta * 4 + (rho >> 2)) + 512 * (rho & 3);
        *(float4*)(wB + rho * WB_STR + col * 4) =
            __ldg((const float4*)(w_ih1 + (size_t)grow * 512) + col);
    }
    for (int i = tid; i < 16 * 128; i += NTHR) {        // w_hh1
        int rho = i >> 7, col = i & 127;
        int grow = (cta * 4 + (rho >> 2)) + 512 * (rho & 3);
        *(float4*)(wB + rho * WB_STR + 512 + col * 4) =
            __ldg((const float4*)(w_hh1 + (size_t)grow * 512) + col);
    }
    for (int i = tid; i < 4 * 256; i += NTHR) {         // attn_out_w
        int rr = i >> 8, col = i & 255;
        *(float4*)(wE + rr * WE_STR + col * 4) =
            __ldg((const float4*)(attn_out_w + (size_t)(cta * 4 + rr) * 1024) + col);
    }
    gbar();

    // warp roles: g = row-group, kq = K-quarter; lane: r = gate/seg, q = batch-quad
    const int g = warp >> 2, kq = warp & 3;
    const int r = lane >> 3, q = lane & 7;
    const int rho = g * 4 + r;
    const float* wAp = wA + rho * WA_STR;
    const float* wBp = wB + rho * WB_STR;

    // phase-D roles: 4 CTAs per batch
    const int db = cta >> 2, dp = cta & 3;
    const int dh = dp * 128 + (tid & 127);     // h-dim this thread owns
    const int dslice = tid >> 7;               // s-slice 0..3

    float c0r = 0.f, c1r = 0.f;
    float biA[4], biB[4];
    if (tid < 128) {
        int jj = tid >> 5, ju = cta * 4 + jj;
#pragma unroll
        for (int rr = 0; rr < 4; rr++) {
            biA[rr] = __ldg(b_ih0 + ju + 512 * rr) + __ldg(b_hh0 + ju + 512 * rr);
            biB[rr] = __ldg(b_ih1 + ju + 512 * rr) + __ldg(b_hh1 + ju + 512 * rr);
        }
    }

    for (int t = 0; t < Tn; t++) {
        const int cur = t & 1, prv = cur ^ 1;

        // ---------- Phase A: LSTM layer 0 gates (K = feed512|h0 512; x-part precomputed) ----------
        {
            // prefetch precomputed x@W term (update threads only)
            float xwv[4];
            if (tid < 128) {
                int b = tid & 31, jj = tid >> 5;
                const float* xwrow = g_xw + (size_t)(t * Bn + b) * 2048 + cta * 4 + jj;
#pragma unroll
                for (int rr = 0; rr < 4; rr++) xwv[rr] = __ldcg(xwrow + 512 * rr);
            }
            unsigned long long A0 = 0ull, A1 = 0ull;
            const int ko = kq * 128;
            mvseg(wAp + 512 + ko,  &g_feedT[ko][0],    128, q, A0, A1);
            mvseg(wAp + 1024 + ko, &g_h0T[prv][ko][0], 128, q, A0, A1);
            float2 v0 = unpack2(A0), v1 = unpack2(A1);
            *(float4*)&sA[kq][g][r][q * 4] = make_float4(v0.x, v0.y, v1.x, v1.y);
            __syncthreads();
            if (tid < 128) {
                int b = tid & 31, jj = tid >> 5;
                float gi = sA[0][jj][0][b] + sA[1][jj][0][b] + sA[2][jj][0][b] + sA[3][jj][0][b] + biA[0] + xwv[0];
                float gf = sA[0][jj][1][b] + sA[1][jj][1][b] + sA[2][jj][1][b] + sA[3][jj][1][b] + biA[1] + xwv[1];
                float gg = sA[0][jj][2][b] + sA[1][jj][2][b] + sA[2][jj][2][b] + sA[3][jj][2][b] + biA[2] + xwv[2];
                float go = sA[0][jj][3][b] + sA[1][jj][3][b] + sA[2][jj][3][b] + sA[3][jj][3][b] + biA[3] + xwv[3];
                c0r = sigm(gf) * c0r + sigm(gi) * tanhf(gg);
                g_h0T[cur][cta * 4 + jj][b] = sigm(go) * tanhf(c0r);
            }
        }
        gbar();

        // ---------- Phase B: LSTM layer 1 gates (K = h0cur 512 | h1prv 512) ----------
        {
            unsigned long long A0 = 0ull, A1 = 0ull;
            const int ko = kq * 128;
            mvseg(wBp + ko,       &g_h0T[cur][ko][0], 128, q, A0, A1);
            mvseg(wBp + 512 + ko, &g_h1T[prv][ko][0], 128, q, A0, A1);
            float2 v0 = unpack2(A0), v1 = unpack2(A1);
            *(float4*)&sA[kq][g][r][q * 4] = make_float4(v0.x, v0.y, v1.x, v1.y);
            __syncthreads();
            if (tid < 128) {
                int b = tid & 31, jj = tid >> 5;
                float gi = sA[0][jj][0][b] + sA[1][jj][0][b] + sA[2][jj][0][b] + sA[3][jj][0][b] + biB[0];
                float gf = sA[0][jj][1][b] + sA[1][jj][1][b] + sA[2][jj][1][b] + sA[3][jj][1][b] + biB[1];
                float gg = sA[0][jj][2][b] + sA[1][jj][2][b] + sA[2][jj][2][b] + sA[3][jj][2][b] + biB[2];
                float go = sA[0][jj][3][b] + sA[1][jj][3][b] + sA[2][jj][3][b] + sA[3][jj][3][b] + biB[3];
                c1r = sigm(gf) * c1r + sigm(gi) * tanhf(gg);
                g_h1T[cur][cta * 4 + jj][b] = sigm(go) * tanhf(c1r);
            }
        }
        gbar();

        // ---------- Phase D: scores -> softmax -> ctx (4 CTAs per batch) ----------
        {
            const int b = db;
            s_q[tid] = __ldca(&g_h1T[cur][tid][b]);
            __syncthreads();
#pragma unroll
            for (int i = 0; i < 8; i++) {
                int sp = warp * 8 + i;
                const float4* er = (const float4*)(g_encq[(size_t)b * Sn + sp]);
                const float4* qr = (const float4*)s_q;
                float acc = 0.f;
#pragma unroll
                for (int c4 = 0; c4 < 4; c4++) {
                    float4 e = __ldca(er + c4 * 32 + lane);
                    float4 q4 = qr[c4 * 32 + lane];
                    acc += e.x * q4.x + e.y * q4.y + e.z * q4.z + e.w * q4.w;
                }
#pragma unroll
                for (int o = 16; o; o >>= 1) acc += __shfl_xor_sync(~0u, acc, o);
                if (lane == 0)
                    s_sc[sp] = (__ldg(mask + b * Sn + sp) == 0) ? NEGV : acc;
            }
            __syncthreads();
            float mv = (tid < 128) ? s_sc[tid] : -3e38f;
#pragma unroll
            for (int o = 16; o; o >>= 1) mv = fmaxf(mv, __shfl_xor_sync(~0u, mv, o));
            if (tid < 128 && lane == 0) s_red[warp] = mv;
            __syncthreads();
            if (tid == 0) {
                float m = s_red[0];
                for (int w = 1; w < 4; w++) m = fmaxf(m, s_red[w]);
                s_red[16] = m;
            }
            __syncthreads();
            float ev = 0.f;
            if (tid < 128) ev = __expf(s_sc[tid] - s_red[16]);
            float sv = ev;
#pragma unroll
            for (int o = 16; o; o >>= 1) sv += __shfl_xor_sync(~0u, sv, o);
            if (tid < 128 && lane == 0) s_red[warp] = sv;
            __syncthreads();
            if (tid == 0) {
                float s = 0.f;
                for (int w = 0; w < 4; w++) s += s_red[w];
                s_red[17] = 1.f / s;
            }
            __syncthreads();
            if (tid < 128) s_sc[tid] = ev * s_red[17];
            __syncthreads();
            // ctx: this CTA covers h in [dp*128, dp*128+128); thread sums 32 s-values
            {
                const int s0 = dslice * 32;
                const float* ep = enc + (size_t)b * Sn * Hn + dh;
                float a[8];
#pragma unroll
                for (int st = 0; st < 8; st++) a[st] = 0.f;
#pragma unroll
                for (int jj2 = 0; jj2 < 4; jj2++)
#pragma unroll
                    for (int st = 0; st < 8; st++) {
                        int s = s0 + st * 4 + jj2;
                        a[st] += s_sc[s] * __ldg(ep + (size_t)s * Hn);
                    }
                float sum = ((a[0] + a[1]) + (a[2] + a[3])) + ((a[4] + a[5]) + (a[6] + a[7]));
                ((float*)sA)[dslice * 128 + (tid & 127)] = sum;
            }
            __syncthreads();
            if (tid < 128) {
                float* pp = (float*)sA;
                g_ctxT[dp * 128 + tid][b] = (pp[tid] + pp[128 + tid]) + (pp[256 + tid] + pp[384 + tid]);
            }
        }
        gbar();

        // ---------- Phase E: input_feed = tanh(attn_out_w @ [ctx512; h1cur512]) ----------
        {
            unsigned long long A0 = 0ull, A1 = 0ull;
            const int seg = kq * 4 + r;   // 16 segments of 64
            const float* src = (seg < 8) ? &g_ctxT[seg * 64][0]
                                         : &g_h1T[cur][(seg - 8) * 64][0];
            mvseg(wE + g * WE_STR + seg * 64, src, 64, q, A0, A1);
            float2 v0 = unpack2(A0), v1 = unpack2(A1);
            *(float4*)&sA[kq][g][r][q * 4] = make_float4(v0.x, v0.y, v1.x, v1.y);
            __syncthreads();
            if (tid < 128) {
                int b = tid & 31, jj = tid >> 5;
                float s = 0.f;
#pragma unroll
                for (int kk = 0; kk < 4; kk++)
#pragma unroll
                    for (int rr = 0; rr < 4; rr++) s += sA[kk][jj][rr][b];
                float f = tanhf(s);
                g_feedT[cta * 4 + jj][b] = f;
                g_dec[b * Tn + t][cta * 4 + jj] = f;
            }
        }
        gbar();
    }
}

// ---------------- 512x512 transpose (attn_in_w -> g_attT) ----------------
__global__ void __launch_bounds__(256)
trans512(const float* __restrict__ src, float* __restrict__ dst)
{
    __shared__ float tile[32][33];
    int bx = blockIdx.x * 32, by = blockIdx.y * 32;
    int tx = threadIdx.x & 31, ty = threadIdx.x >> 5;   // 32x8
#pragma unroll
    for (int i = 0; i < 4; i++)
        tile[ty + i * 8][tx] = __ldg(src + (size_t)(by + ty + i * 8) * 512 + bx + tx);
    __syncthreads();
#pragma unroll
    for (int i = 0; i < 4; i++)
        dst[(size_t)(bx + ty + i * 8) * 512 + by + tx] = tile[tx][ty + i * 8];
}

// ---------------- SIMT f32x2 gemm: C = A @ W^T (+bias), fp32 out; W row stride ldw ----------------
__global__ void __launch_bounds__(256)
gemm_nt(const float* __restrict__ A, const float* __restrict__ W,
        const float* __restrict__ bias, float* __restrict__ C,
        int M, int N, int K, int ldw)
{
    __shared__ __align__(16) float As[16][128];
    __shared__ __align__(16) float Ws[16][128];
    const int m0 = blockIdx.y * 128, n0 = blockIdx.x * 128;
    const int tid = threadIdx.x;
    const int tx = tid & 15, ty = tid >> 4;
    const int lrow = tid >> 1, lcol = (tid & 1) * 8;

    unsigned long long acc2[8][4];
#pragma unroll
    for (int i = 0; i < 8; i++)
#pragma unroll
        for (int jj = 0; jj < 4; jj++) acc2[i][jj] = 0ull;

    const float* Aload = A + (size_t)(m0 + lrow) * K + lcol;
    const float* Wload = W + (size_t)(n0 + lrow) * ldw + lcol;

    for (int k0 = 0; k0 < K; k0 += 16) {
        float4 a0 = __ldg((const float4*)(Aload + k0));
        float4 a1 = __ldg((const float4*)(Aload + k0 + 4));
        float4 w0 = __ldg((const float4*)(Wload + k0));
        float4 w1 = __ldg((const float4*)(Wload + k0 + 4));
        __syncthreads();
        As[lcol + 0][lrow] = a0.x; As[lcol + 1][lrow] = a0.y;
        As[lcol + 2][lrow] = a0.z; As[lcol + 3][lrow] = a0.w;
        As[lcol + 4][lrow] = a1.x; As[lcol + 5][lrow] = a1.y;
        As[lcol + 6][lrow] = a1.z; As[lcol + 7][lrow] = a1.w;
        Ws[lcol + 0][lrow] = w0.x; Ws[lcol + 1][lrow] = w0.y;
        Ws[lcol + 2][lrow] = w0.z; Ws[lcol + 3][lrow] = w0.w;
        Ws[lcol + 4][lrow] = w1.x; Ws[lcol + 5][lrow] = w1.y;
        Ws[lcol + 6][lrow] = w1.z; Ws[lcol + 7][lrow] = w1.w;
        __syncthreads();
#pragma unroll
        for (int kk = 0; kk < 16; kk++) {
            float4 av0 = *(const float4*)&As[kk][ty * 8];
            float4 av1 = *(const float4*)&As[kk][ty * 8 + 4];
            const ulonglong2* wp = (const ulonglong2*)&Ws[kk][tx * 8];
            ulonglong2 b01 = wp[0], b23 = wp[1];
            float a8[8] = {av0.x, av0.y, av0.z, av0.w, av1.x, av1.y, av1.z, av1.w};
#pragma unroll
            for (int i = 0; i < 8; i++) {
                unsigned long long a2 = pack2(a8[i]);
                ffma2(acc2[i][0], a2, b01.x);
                ffma2(acc2[i][1], a2, b01.y);
                ffma2(acc2[i][2], a2, b23.x);
                ffma2(acc2[i][3], a2, b23.y);
            }
        }
    }
#pragma unroll
    for (int i = 0; i < 8; i++) {
        float* Crow = C + (size_t)(m0 + ty * 8 + i) * N + n0 + tx * 8;
#pragma unroll
        for (int jj = 0; jj < 4; jj++) {
            float2 v = unpack2(acc2[i][jj]);
            if (bias) {
                v.x += __ldg(bias + n0 + tx * 8 + 2 * jj);
                v.y += __ldg(bias + n0 + tx * 8 + 2 * jj + 1);
            }
            *(float2*)(Crow + 2 * jj) = v;
        }
    }
}

// ---------------- SIMT f32x2 gemm (out_proj) -> bf16 hi/lo ----------------
__device__ __forceinline__ void split_bf16(float v, __nv_bfloat16& h, __nv_bfloat16& l)
{
    h = __float2bfloat16(v);
    l = __float2bfloat16(v - __bfloat162float(h));
}

__global__ void __launch_bounds__(256)
gemm_nt_split(const float* __restrict__ A, const float* __restrict__ W,
              const float* __restrict__ bias,
              __nv_bfloat16* __restrict__ Chi, __nv_bfloat16* __restrict__ Clo,
              int M, int N, int K)
{
    __shared__ __align__(16) float As[16][128];
    __shared__ __align__(16) float Ws[16][128];
    const int m0 = blockIdx.y * 128, n0 = blockIdx.x * 128;
    const int tid = threadIdx.x;
    const int tx = tid & 15, ty = tid >> 4;
    const int lrow = tid >> 1, lcol = (tid & 1) * 8;

    unsigned long long acc2[8][4];
#pragma unroll
    for (int i = 0; i < 8; i++)
#pragma unroll
        for (int jj = 0; jj < 4; jj++) acc2[i][jj] = 0ull;

    const float* Aload = A + (size_t)(m0 + lrow) * K + lcol;
    const float* Wload = W + (size_t)(n0 + lrow) * K + lcol;

    for (int k0 = 0; k0 < K; k0 += 16) {
        float4 a0 = __ldg((const float4*)(Aload + k0));
        float4 a1 = __ldg((const float4*)(Aload + k0 + 4));
        float4 w0 = __ldg((const float4*)(Wload + k0));
        float4 w1 = __ldg((const float4*)(Wload + k0 + 4));
        __syncthreads();
        As[lcol + 0][lrow] = a0.x; As[lcol + 1][lrow] = a0.y;
        As[lcol + 2][lrow] = a0.z; As[lcol + 3][lrow] = a0.w;
        As[lcol + 4][lrow] = a1.x; As[lcol + 5][lrow] = a1.y;
        As[lcol + 6][lrow] = a1.z; As[lcol + 7][lrow] = a1.w;
        Ws[lcol + 0][lrow] = w0.x; Ws[lcol + 1][lrow] = w0.y;
        Ws[lcol + 2][lrow] = w0.z; Ws[lcol + 3][lrow] = w0.w;
        Ws[lcol + 4][lrow] = w1.x; Ws[lcol + 5][lrow] = w1.y;
        Ws[lcol + 6][lrow] = w1.z; Ws[lcol + 7][lrow] = w1.w;
        __syncthreads();
#pragma unroll
        for (int kk = 0; kk < 16; kk++) {
            float4 av0 = *(const float4*)&As[kk][ty * 8];
            float4 av1 = *(const float4*)&As[kk][ty * 8 + 4];
            const ulonglong2* wp = (const ulonglong2*)&Ws[kk][tx * 8];
            ulonglong2 b01 = wp[0], b23 = wp[1];
            float a8[8] = {av0.x, av0.y, av0.z, av0.w, av1.x, av1.y, av1.z, av1.w};
#pragma unroll
            for (int i = 0; i < 8; i++) {
                unsigned long long a2 = pack2(a8[i]);
                ffma2(acc2[i][0], a2, b01.x);
                ffma2(acc2[i][1], a2, b01.y);
                ffma2(acc2[i][2], a2, b23.x);
                ffma2(acc2[i][3], a2, b23.y);
            }
        }
    }
#pragma unroll
    for (int i = 0; i < 8; i++) {
        size_t rowoff = (size_t)(m0 + ty * 8 + i) * N + n0 + tx * 8;
        unsigned short tmph[8], tmpl[8];
#pragma unroll
        for (int jj = 0; jj < 4; jj++) {
            float2 v = unpack2(acc2[i][jj]);
            v.x += __ldg(bias + n0 + tx * 8 + 2 * jj);
            v.y += __ldg(bias + n0 + tx * 8 + 2 * jj + 1);
            __nv_bfloat16 h0, l0, h1, l1;
            split_bf16(v.x, h0, l0);
            split_bf16(v.y, h1, l1);
            tmph[2 * jj] = __bfloat16_as_ushort(h0); tmph[2 * jj + 1] = __bfloat16_as_ushort(h1);
            tmpl[2 * jj] = __bfloat16_as_ushort(l0); tmpl[2 * jj + 1] = __bfloat16_as_ushort(l1);
        }
        uint2 H, L, H2, L2;
        H.x = (uint32_t)tmph[0] | ((uint32_t)tmph[1] << 16);
        H.y = (uint32_t)tmph[2] | ((uint32_t)tmph[3] << 16);
        L.x = (uint32_t)tmpl[0] | ((uint32_t)tmpl[1] << 16);
        L.y = (uint32_t)tmpl[2] | ((uint32_t)tmpl[3] << 16);
        H2.x = (uint32_t)tmph[4] | ((uint32_t)tmph[5] << 16);
        H2.y = (uint32_t)tmph[6] | ((uint32_t)tmph[7] << 16);
        L2.x = (uint32_t)tmpl[4] | ((uint32_t)tmpl[5] << 16);
        L2.y = (uint32_t)tmpl[6] | ((uint32_t)tmpl[7] << 16);
        *(uint2*)(Chi + rowoff) = H;  *(uint2*)(Chi + rowoff + 4) = H2;
        *(uint2*)(Clo + rowoff) = L;  *(uint2*)(Clo + rowoff + 4) = L2;
    }
}

// ---------------- fp32 -> bf16 hi/lo split (embed) ----------------
__global__ void __launch_bounds__(256)
conv_split(const float4* __restrict__ src, uint2* __restrict__ hi, uint2* __restrict__ lo)
{
    int i = blockIdx.x * 256 + threadIdx.x;
    float4 v = __ldg(src + i);
    __nv_bfloat16 h0, l0, h1, l1, h2, l2, h3, l3;
    split_bf16(v.x, h0, l0); split_bf16(v.y, h1, l1);
    split_bf16(v.z, h2, l2); split_bf16(v.w, h3, l3);
    uint2 H, L;
    H.x = (uint32_t)__bfloat16_as_ushort(h0) | ((uint32_t)__bfloat16_as_ushort(h1) << 16);
    H.y = (uint32_t)__bfloat16_as_ushort(h2) | ((uint32_t)__bfloat16_as_ushort(h3) << 16);
    L.x = (uint32_t)__bfloat16_as_ushort(l0) | ((uint32_t)__bfloat16_as_ushort(l1) << 16);
    L.y = (uint32_t)__bfloat16_as_ushort(l2) | ((uint32_t)__bfloat16_as_ushort(l3) << 16);
    hi[i] = H; lo[i] = L;
}

// ---------------- mma.sync bf16 3-pass GEMM: C = A @ B^T ----------------
static constexpr int KC = 32;
static constexpr int NCHUNK = En / KC;
static constexpr int ROWB = 80;
static constexpr int MATB = 128 * ROWB;
static constexpr int STAGEB = 4 * MATB;
static constexpr int GSMEM2 = 2 * STAGEB;

__device__ __forceinline__ void ldmA(uint32_t* r, uint32_t addr)
{
    asm volatile("ldmatrix.sync.aligned.m8n8.x4.shared.b16 {%0,%1,%2,%3}, [%4];"
                 : "=r"(r[0]), "=r"(r[1]), "=r"(r[2]), "=r"(r[3]) : "r"(addr));
}
__device__ __forceinline__ void ldmB(uint32_t* r, uint32_t addr)
{
    asm volatile("ldmatrix.sync.aligned.m8n8.x2.shared.b16 {%0,%1}, [%2];"
                 : "=r"(r[0]), "=r"(r[1]) : "r"(addr));
}
__device__ __forceinline__ void mma16816(float* d, const uint32_t* a, const uint32_t* b)
{
    asm volatile("mma.sync.aligned.m16n8k16.row.col.f32.bf16.bf16.f32 "
                 "{%0,%1,%2,%3}, {%4,%5,%6,%7}, {%8,%9}, {%0,%1,%2,%3};"
                 : "+f"(d[0]), "+f"(d[1]), "+f"(d[2]), "+f"(d[3])
                 : "r"(a[0]), "r"(a[1]), "r"(a[2]), "r"(a[3]), "r"(b[0]), "r"(b[1]));
}

__global__ void __launch_bounds__(256, 2)
gemm_bf16(const __nv_bfloat16* __restrict__ Ahi, const __nv_bfloat16* __restrict__ Alo,
          const __nv_bfloat16* __restrict__ Bhi, const __nv_bfloat16* __restrict__ Blo,
          float* __restrict__ C, int N, int K)
{
    extern __shared__ char smem[];
    const uint32_t su = s2u(smem);
    const int tid = threadIdx.x, wid = tid >> 5, lane = tid & 31;
    const int m0 = blockIdx.x * 128, n0 = blockIdx.y * 128;
    const int wm = wid & 1, wn = wid >> 1;

    const int ci0 = tid;
    auto load_stage = [&](int chunk) {
        const uint32_t sb = su + (chunk & 1) * STAGEB;
#pragma unroll
        for (int r8 = 0; r8 < 8; r8++) {
            int ci = ci0 + r8 * 256;
            int mat = ci >> 9, rem = ci & 511;
            int row = rem >> 2, seg = rem & 3;
            const __nv_bfloat16* g;
            if (mat == 0)      g = Ahi + (size_t)(m0 + row) * K + chunk * KC + seg * 8;
            else if (mat == 1) g = Alo + (size_t)(m0 + row) * K + chunk * KC + seg * 8;
            else if (mat == 2) g = Bhi + (size_t)(n0 + row) * K + chunk * KC + seg * 8;
            else               g = Blo + (size_t)(n0 + row) * K + chunk * KC + seg * 8;
            cp16(sb + mat * MATB + row * ROWB + seg * 16, g);
        }
        asm volatile("cp.async.commit_group;" ::: "memory");
    };

    float acc[4][4][4];
#pragma unroll
    for (int i = 0; i < 4; i++)
#pragma unroll
        for (int jj = 0; jj < 4; jj++)
#pragma unroll
            for (int k = 0; k < 4; k++) acc[i][jj][k] = 0.f;

    load_stage(0);
    load_stage(1);

    for (int c = 0; c < NCHUNK; c++) {
        if (c < NCHUNK - 1) asm volatile("cp.async.wait_group 1;" ::: "memory");
        else                asm volatile("cp.async.wait_group 0;" ::: "memory");
        __syncthreads();
        const uint32_t sb = su + (c & 1) * STAGEB;
        const uint32_t aHiB = sb,            aLoB = sb + MATB;
        const uint32_t bHiB = sb + 2 * MATB, bLoB = sb + 3 * MATB;
#pragma unroll
        for (int ks = 0; ks < 2; ks++) {
            const uint32_t aoff = (uint32_t)((wm * 64 + (lane & 15)) * ROWB
                                             + (ks * 16 + (lane >> 4) * 8) * 2);
            const int l = lane & 15;
            const uint32_t boff = (uint32_t)((wn * 32 + (l & 7)) * ROWB
                                             + (ks * 16 + (l >> 3) * 8) * 2);
            uint32_t ah[4][4], al[4][4], bh[4][2], bl[4][2];
#pragma unroll
            for (int mi = 0; mi < 4; mi++) {
                ldmA(ah[mi], aHiB + aoff + mi * 16 * ROWB);
                ldmA(al[mi], aLoB + aoff + mi * 16 * ROWB);
            }
#pragma unroll
            for (int ni = 0; ni < 4; ni++) {
                ldmB(bh[ni], bHiB + boff + ni * 8 * ROWB);
                ldmB(bl[ni], bLoB + boff + ni * 8 * ROWB);
            }
#pragma unroll
            for (int mi = 0; mi < 4; mi++)
#pragma unroll
                for (int ni = 0; ni < 4; ni++) {
                    mma16816(acc[mi][ni], ah[mi], bh[ni]);
                    mma16816(acc[mi][ni], ah[mi], bl[ni]);
                    mma16816(acc[mi][ni], al[mi], bh[ni]);
                }
        }
        __syncthreads();
        if (c + 2 < NCHUNK) load_stage(c + 2);
    }

    const int mbase = m0 + wm * 64 + (lane >> 2);
    const int nbase = n0 + wn * 32 + (lane & 3) * 2;
#pragma unroll
    for (int mi = 0; mi < 4; mi++)
#pragma unroll
        for (int ni = 0; ni < 4; ni++) {
            float* p0 = C + (size_t)(mbase + mi * 16) * N + nbase + ni * 8;
            float* p1 = C + (size_t)(mbase + mi * 16 + 8) * N + nbase + ni * 8;
            *(float2*)p0 = make_float2(acc[mi][ni][0], acc[mi][ni][1]);
            *(float2*)p1 = make_float2(acc[mi][ni][2], acc[mi][ni][3]);
        }
}

extern "C" void kernel_launch(void* const* d_in, const int* in_sizes, int n_in,
                              void* d_out, int out_size)
{
    const int*   tokens     = (const int*)d_in[0];
    const float* enc        = (const float*)d_in[1];
    const int*   mask       = (const int*)d_in[2];
    const float* embed      = (const float*)d_in[3];
    const float* w_ih0      = (const float*)d_in[4];
    const float* w_hh0      = (const float*)d_in[5];
    const float* b_ih0      = (const float*)d_in[6];
    const float* b_hh0      = (const float*)d_in[7];
    const float* w_ih1      = (const float*)d_in[8];
    const float* w_hh1      = (const float*)d_in[9];
    const float* b_ih1      = (const float*)d_in[10];
    const float* b_hh1      = (const float*)d_in[11];
    const float* attn_in_w  = (const float*)d_in[12];
    const float* attn_out_w = (const float*)d_in[13];
    const float* out_proj_w = (const float*)d_in[14];
    const float* out_proj_b = (const float*)d_in[15];
    float* out = (float*)d_out;

    float *dec, *encq, *attT, *xrow, *xw;
    __nv_bfloat16 *Ahi, *Alo, *Bhi, *Blo;
    cudaGetSymbolAddress((void**)&dec, g_dec);
    cudaGetSymbolAddress((void**)&encq, g_encq);
    cudaGetSymbolAddress((void**)&attT, g_attT);
    cudaGetSymbolAddress((void**)&xrow, g_x);
    cudaGetSymbolAddress((void**)&xw, g_xw);
    cudaGetSymbolAddress((void**)&Ahi, g_Ahi);
    cudaGetSymbolAddress((void**)&Alo, g_Alo);
    cudaGetSymbolAddress((void**)&Bhi, g_Bhi);
    cudaGetSymbolAddress((void**)&Blo, g_Blo);

    cudaFuncSetAttribute(gemm_bf16, cudaFuncAttributeMaxDynamicSharedMemorySize, GSMEM2);
    cudaFuncSetAttribute(recurrent_kernel, cudaFuncAttributeMaxDynamicSharedMemorySize, DSMEM);

    static cudaStream_t s2 = nullptr;
    static cudaEvent_t evA = nullptr, evB = nullptr;
    if (!s2) {
        cudaStreamCreateWithFlags(&s2, cudaStreamNonBlocking);
        cudaEventCreateWithFlags(&evA, cudaEventDisableTiming);
        cudaEventCreateWithFlags(&evB, cudaEventDisableTiming);
    }

    // side stream: embed hi/lo conversion (independent; overlaps pre-GEMMs + recurrence)
    cudaEventRecord(evA, 0);
    cudaStreamWaitEvent(s2, evA, 0);
    conv_split<<<Vn * En / 1024, 256, 0, s2>>>((const float4*)embed, (uint2*)Bhi, (uint2*)Blo);
    cudaEventRecord(evB, s2);

    // pre-GEMMs: encq = enc @ attn_in_w^T-less (phase C removal); xw = x @ w_ih0[:, :512]^T
    trans512<<<dim3(16, 16), 256>>>(attn_in_w, attT);
    gather_x<<<256, 256>>>(tokens, embed);
    gemm_nt<<<dim3(Hn / 128, (Bn * Sn) / 128), 256>>>(enc, attT, nullptr, encq,
                                                      Bn * Sn, Hn, Hn, Hn);
    gemm_nt<<<dim3(2048 / 128, (Bn * Tn) / 128), 256>>>(xrow, w_ih0, nullptr, xw,
                                                        Bn * Tn, 2048, 512, 1024);
    recurrent_kernel<<<NCTA, NTHR, DSMEM>>>(enc, mask,
                                            w_ih0, w_hh0, b_ih0, b_hh0,
                                            w_ih1, w_hh1, b_ih1, b_hh1,
                                            attn_out_w);
    gemm_nt_split<<<dim3(En / 128, (Bn * Tn) / 128), 256>>>(dec, out_proj_w, out_proj_b,
                                                            Ahi, Alo, Bn * Tn, En, Hn);
    cudaStreamWaitEvent(0, evB, 0);
    gemm_bf16<<<dim3((Bn * Tn) / 128, Vn / 128), 256, GSMEM2>>>(Ahi, Alo, Bhi, Blo, out, Vn, En);
}

// round 12
// speedup vs baseline: 1.7794x; 1.2378x over previous
#include <cuda_runtime.h>
#include <cuda_bf16.h>
#include <cstdint>

#define NCTA 128
#define NTHR 512
static constexpr int Bn = 32, Tn = 64, Sn = 128, Hn = 512, En = 512, Vn = 32000;
static constexpr float NEGV = -1e4f;

// ---------------- device scratch (allocation-free) ----------------
__device__ __align__(16) float g_x[Bn * Tn][En];      // gathered embeddings, row = t*Bn+b
__device__ __align__(16) float g_xw[Bn * Tn * 2048];  // x @ w_ih0[:, :512]^T
__device__ __align__(16) float g_feedT[Hn][Bn];
__device__ __align__(16) float g_h0T[2][Hn][Bn];
__device__ __align__(16) float g_h1T[2][Hn][Bn];
__device__ __align__(16) float g_ctxT[Hn][Bn];
__device__ __align__(16) float g_dec[Bn * Tn][Hn];
__device__ __align__(16) float g_encq[Bn * Sn][Hn];   // enc @ attn_in_w
__device__ __align__(16) float g_attT[Hn * Hn];       // attn_in_w transposed
__device__ __nv_bfloat16 g_Ahi[Bn * Tn * En];
__device__ __nv_bfloat16 g_Alo[Bn * Tn * En];
__device__ __nv_bfloat16 g_Bhi[Vn * En];
__device__ __nv_bfloat16 g_Blo[Vn * En];
__device__ unsigned g_count;
__device__ volatile unsigned g_gen;

// ---------------- small helpers ----------------
__device__ __forceinline__ uint32_t s2u(const void* p)
{
    uint32_t a;
    asm("{ .reg .u64 t; cvta.to.shared.u64 t, %1; cvt.u32.u64 %0, t; }" : "=r"(a) : "l"(p));
    return a;
}
__device__ __forceinline__ void cp16(uint32_t s, const void* g)
{
    asm volatile("cp.async.cg.shared.global [%0], [%1], 16;" :: "r"(s), "l"(g) : "memory");
}
__device__ __forceinline__ float sigm(float x) { return 1.f / (1.f + __expf(-x)); }

__device__ __forceinline__ unsigned long long pack2(float x)
{ unsigned long long r; asm("mov.b64 %0, {%1, %1};" : "=l"(r) : "f"(x)); return r; }
__device__ __forceinline__ unsigned long long pack2f(float x, float y)
{ unsigned long long r; asm("mov.b64 %0, {%1, %2};" : "=l"(r) : "f"(x), "f"(y)); return r; }
__device__ __forceinline__ void ffma2(unsigned long long& d, unsigned long long a, unsigned long long b)
{ asm("fma.rn.f32x2 %0, %1, %2, %0;" : "+l"(d) : "l"(a), "l"(b)); }
__device__ __forceinline__ float2 unpack2(unsigned long long v)
{ float2 r; asm("mov.b64 {%0, %1}, %2;" : "=f"(r.x), "=f"(r.y) : "l"(v)); return r; }

// ---------------- grid barrier (all 128 CTAs co-resident) ----------------
__device__ __forceinline__ void gbar()
{
    __threadfence();
    __syncthreads();
    if (threadIdx.x == 0) {
        unsigned g = g_gen;
        unsigned a = atomicAdd(&g_count, 1u);
        if (a == NCTA - 1u) {
            g_count = 0u;
            __threadfence();
            g_gen = g + 1u;
        } else {
            while (g_gen == g) { }
        }
    }
    __syncthreads();
    __threadfence();
}

// dynamic smem: packed f32x2 weights, [warp][kpair][row] order
// wA: 16 w * 32 kp * 16 r ; wB same ; wE: 16 w * 32 kp * 4 r
static constexpr int WA2 = 8192, WB2 = 8192, WE2 = 2048;     // float2 counts
static constexpr int DSMEM = (WA2 + WB2 + WE2) * 8;          // 147456 bytes

// ---------------- embed gather: g_x[t*Bn+b] = embed[tokens[b][t]] ----------------
__global__ void __launch_bounds__(256)
gather_x(const int* __restrict__ tokens, const float* __restrict__ embed)
{
    int p = blockIdx.x * 8 + (threadIdx.x >> 5);  // 0..2047 = t*32+b
    int lane = threadIdx.x & 31;
    int t = p >> 5, b = p & 31;
    int tok = __ldg(tokens + b * Tn + t);
    const float4* er = (const float4*)(embed + (size_t)tok * En);
    float4* dr = (float4*)g_x[t * Bn + b];
#pragma unroll
    for (int i = 0; i < 4; i++)
        dr[i * 32 + lane] = __ldg(er + i * 32 + lane);
}

// warp-sliced matvec over one 64-k slice: NR rows, act[k][32] global, weights smem f32x2.
// lane = batch. Result partials (even+odd folded) -> red[warp][r][lane].
template<int NR>
__device__ __forceinline__ void mv16(const float2* __restrict__ wslice,   // smem, [kp][NR]
                                     const float* __restrict__ act,       // global, 64 k rows
                                     int lane, float* __restrict__ red)   // [NR][32] out
{
    unsigned long long acc[NR];
#pragma unroll
    for (int r = 0; r < NR; r++) acc[r] = 0ull;
#pragma unroll 8
    for (int kp = 0; kp < 32; kp++) {
        float a0 = __ldca(act + kp * 64 + lane);
        float a1 = __ldca(act + kp * 64 + 32 + lane);
        unsigned long long av = pack2f(a0, a1);
        const ulonglong2* wrow = (const ulonglong2*)(wslice + kp * NR);
#pragma unroll
        for (int rp = 0; rp < NR / 2; rp++) {
            ulonglong2 wv = wrow[rp];
            ffma2(acc[rp * 2], wv.x, av);
            ffma2(acc[rp * 2 + 1], wv.y, av);
        }
    }
#pragma unroll
    for (int r = 0; r < NR; r++) {
        float2 v = unpack2(acc[r]);
        red[r * 32 + lane] = v.x + v.y;
    }
}

// ---------------- persistent recurrence (512 threads: 16 warps) ----------------
__global__ void __launch_bounds__(NTHR, 1)
recurrent_kernel(const float* __restrict__ enc,
                 const int* __restrict__ mask,
                 const float* __restrict__ w_ih0, const float* __restrict__ w_hh0,
                 const float* __restrict__ b_ih0, const float* __restrict__ b_hh0,
                 const float* __restrict__ w_ih1, const float* __restrict__ w_hh1,
                 const float* __restrict__ b_ih1, const float* __restrict__ b_hh1,
                 const float* __restrict__ attn_out_w)
{
    extern __shared__ __align__(16) float2 wsm2[];
    float2* wA = wsm2;
    float2* wB = wA + WA2;
    float2* wE = wB + WB2;

    const int tid = threadIdx.x, cta = blockIdx.x;
    const int warp = tid >> 5, lane = tid & 31;
    const int gtid = cta * NTHR + tid;

    __shared__ __align__(16) float sAred[16][16][32];   // [warp][row][batch] partials (32KB)
    __shared__ __align__(16) float gs[16][32];
    __shared__ __align__(16) float s_q[512];
    __shared__ float s_sc[128];
    __shared__ float s_red[32];

    // ---- init recurrent state ----
    for (int i = gtid; i < Hn * Bn; i += NCTA * NTHR) {
        (&g_feedT[0][0])[i] = 0.f;
        (&g_h0T[0][0][0])[i] = 0.f; (&g_h0T[1][0][0])[i] = 0.f;
        (&g_h1T[0][0][0])[i] = 0.f; (&g_h1T[1][0][0])[i] = 0.f;
    }

    // ---- stage packed weights: entry i = ((w*32+kp)*NR + r) ----
    for (int i = tid; i < WA2; i += NTHR) {             // phase A: feed(512)|h0(512)
        int w = i >> 9, kp = (i >> 4) & 31, r = i & 15;
        int grow = (r & 3) * 512 + cta * 4 + (r >> 2);
        int k = w * 64 + kp * 2;
        float2 v;
        if (k < 512) {
            const float* p = w_ih0 + (size_t)grow * 1024 + 512 + k;
            v = make_float2(__ldg(p), __ldg(p + 1));
        } else {
            const float* p = w_hh0 + (size_t)grow * 512 + (k - 512);
            v = make_float2(__ldg(p), __ldg(p + 1));
        }
        wA[i] = v;
    }
    for (int i = tid; i < WB2; i += NTHR) {             // phase B: h0cur(512)|h1prv(512)
        int w = i >> 9, kp = (i >> 4) & 31, r = i & 15;
        int grow = (r & 3) * 512 + cta * 4 + (r >> 2);
        int k = w * 64 + kp * 2;
        float2 v;
        if (k < 512) {
            const float* p = w_ih1 + (size_t)grow * 512 + k;
            v = make_float2(__ldg(p), __ldg(p + 1));
        } else {
            const float* p = w_hh1 + (size_t)grow * 512 + (k - 512);
            v = make_float2(__ldg(p), __ldg(p + 1));
        }
        wB[i] = v;
    }
    for (int i = tid; i < WE2; i += NTHR) {             // phase E: ctx(512)|h1(512), 4 rows
        int w = i >> 7, kp = (i >> 2) & 31, r = i & 3;
        int k = w * 64 + kp * 2;
        const float* p = attn_out_w + (size_t)(cta * 4 + r) * 1024 + k;
        wE[i] = make_float2(__ldg(p), __ldg(p + 1));
    }
    gbar();

    // phase-D roles: 4 CTAs per batch
    const int db = cta >> 2, dp = cta & 3;
    const int dh = dp * 128 + (tid & 127);
    const int dslice = tid >> 7;

    float c0r = 0.f, c1r = 0.f;
    float biA[4], biB[4];
    if (tid < 128) {
        int jj = tid >> 5, ju = cta * 4 + jj;
#pragma unroll
        for (int rr = 0; rr < 4; rr++) {
            biA[rr] = __ldg(b_ih0 + ju + 512 * rr) + __ldg(b_hh0 + ju + 512 * rr);
            biB[rr] = __ldg(b_ih1 + ju + 512 * rr) + __ldg(b_hh1 + ju + 512 * rr);
        }
    }

    for (int t = 0; t < Tn; t++) {
        const int cur = t & 1, prv = cur ^ 1;

        // ---------- Phase A: LSTM layer 0 gates ----------
        {
            float xwv[4];
            if (tid < 128) {
                int b = tid & 31, jj = tid >> 5;
                const float* xwrow = g_xw + (size_t)(t * Bn + b) * 2048 + cta * 4 + jj;
#pragma unroll
                for (int rr = 0; rr < 4; rr++) xwv[rr] = __ldcg(xwrow + 512 * rr);
            }
            const float* act = (warp < 8) ? &g_feedT[warp * 64][0]
                                          : &g_h0T[prv][(warp - 8) * 64][0];
            mv16<16>(wA + warp * 32 * 16, act, lane, &sAred[warp][0][0]);
            __syncthreads();
            {   // 512-thread reduction: (row, b)
                int row = tid >> 5, b = tid & 31;
                float s = 0.f;
#pragma unroll
                for (int w = 0; w < 16; w++) s += sAred[w][row][b];
                gs[row][b] = s;
            }
            __syncthreads();
            if (tid < 128) {
                int b = tid & 31, jj = tid >> 5;
                float gi = gs[jj * 4 + 0][b] + biA[0] + xwv[0];
                float gf = gs[jj * 4 + 1][b] + biA[1] + xwv[1];
                float gg = gs[jj * 4 + 2][b] + biA[2] + xwv[2];
                float go = gs[jj * 4 + 3][b] + biA[3] + xwv[3];
                c0r = sigm(gf) * c0r + sigm(gi) * tanhf(gg);
                g_h0T[cur][cta * 4 + jj][b] = sigm(go) * tanhf(c0r);
            }
        }
        gbar();

        // ---------- Phase B: LSTM layer 1 gates ----------
        {
            const float* act = (warp < 8) ? &g_h0T[cur][warp * 64][0]
                                          : &g_h1T[prv][(warp - 8) * 64][0];
            mv16<16>(wB + warp * 32 * 16, act, lane, &sAred[warp][0][0]);
            __syncthreads();
            {
                int row = tid >> 5, b = tid & 31;
                float s = 0.f;
#pragma unroll
                for (int w = 0; w < 16; w++) s += sAred[w][row][b];
                gs[row][b] = s;
            }
            __syncthreads();
            if (tid < 128) {
                int b = tid & 31, jj = tid >> 5;
                float gi = gs[jj * 4 + 0][b] + biB[0];
                float gf = gs[jj * 4 + 1][b] + biB[1];
                float gg = gs[jj * 4 + 2][b] + biB[2];
                float go = gs[jj * 4 + 3][b] + biB[3];
                c1r = sigm(gf) * c1r + sigm(gi) * tanhf(gg);
                g_h1T[cur][cta * 4 + jj][b] = sigm(go) * tanhf(c1r);
            }
        }
        gbar();

        // ---------- Phase D: scores -> softmax -> ctx (4 CTAs per batch) ----------
        {
            const int b = db;
            s_q[tid] = __ldca(&g_h1T[cur][tid][b]);
            __syncthreads();
#pragma unroll
            for (int i = 0; i < 8; i++) {
                int sp = warp * 8 + i;
                const float4* er = (const float4*)(g_encq[(size_t)b * Sn + sp]);
                const float4* qr = (const float4*)s_q;
                float acc = 0.f;
#pragma unroll
                for (int c4 = 0; c4 < 4; c4++) {
                    float4 e = __ldca(er + c4 * 32 + lane);
                    float4 q4 = qr[c4 * 32 + lane];
                    acc += e.x * q4.x + e.y * q4.y + e.z * q4.z + e.w * q4.w;
                }
#pragma unroll
                for (int o = 16; o; o >>= 1) acc += __shfl_xor_sync(~0u, acc, o);
                if (lane == 0)
                    s_sc[sp] = (__ldg(mask + b * Sn + sp) == 0) ? NEGV : acc;
            }
            __syncthreads();
            float mv = (tid < 128) ? s_sc[tid] : -3e38f;
#pragma unroll
            for (int o = 16; o; o >>= 1) mv = fmaxf(mv, __shfl_xor_sync(~0u, mv, o));
            if (tid < 128 && lane == 0) s_red[warp] = mv;
            __syncthreads();
            if (tid == 0) {
                float m = s_red[0];
                for (int w = 1; w < 4; w++) m = fmaxf(m, s_red[w]);
                s_red[16] = m;
            }
            __syncthreads();
            float ev = 0.f;
            if (tid < 128) ev = __expf(s_sc[tid] - s_red[16]);
            float sv = ev;
#pragma unroll
            for (int o = 16; o; o >>= 1) sv += __shfl_xor_sync(~0u, sv, o);
            if (tid < 128 && lane == 0) s_red[warp] = sv;
            __syncthreads();
            if (tid == 0) {
                float s = 0.f;
                for (int w = 0; w < 4; w++) s += s_red[w];
                s_red[17] = 1.f / s;
            }
            __syncthreads();
            if (tid < 128) s_sc[tid] = ev * s_red[17];
            __syncthreads();
            {
                const int s0 = dslice * 32;
                const float* ep = enc + (size_t)b * Sn * Hn + dh;
                float a[8];
#pragma unroll
                for (int st = 0; st < 8; st++) a[st] = 0.f;
#pragma unroll
                for (int jj2 = 0; jj2 < 4; jj2++)
#pragma unroll
                    for (int st = 0; st < 8; st++) {
                        int s = s0 + st * 4 + jj2;
                        a[st] += s_sc[s] * __ldg(ep + (size_t)s * Hn);
                    }
                float sum = ((a[0] + a[1]) + (a[2] + a[3])) + ((a[4] + a[5]) + (a[6] + a[7]));
                ((float*)sAred)[dslice * 128 + (tid & 127)] = sum;
            }
            __syncthreads();
            if (tid < 128) {
                float* pp = (float*)sAred;
                g_ctxT[dp * 128 + tid][db] = (pp[tid] + pp[128 + tid]) + (pp[256 + tid] + pp[384 + tid]);
            }
        }
        gbar();

        // ---------- Phase E: input_feed = tanh(attn_out_w @ [ctx512; h1cur512]) ----------
        {
            const float* act = (warp < 8) ? &g_ctxT[warp * 64][0]
                                          : &g_h1T[cur][(warp - 8) * 64][0];
            mv16<4>(wE + warp * 32 * 4, act, lane, &sAred[warp][0][0]);
            __syncthreads();
            if (tid < 128) {
                int b = tid & 31, row = tid >> 5;
                float s = 0.f;
#pragma unroll
                for (int w = 0; w < 16; w++) s += sAred[w][row][b];
                float f = tanhf(s);
                g_feedT[cta * 4 + row][b] = f;
                g_dec[b * Tn + t][cta * 4 + row] = f;
            }
        }
        gbar();
    }
}

// ---------------- 512x512 transpose (attn_in_w -> g_attT) ----------------
__global__ void __launch_bounds__(256)
trans512(const float* __restrict__ src, float* __restrict__ dst)
{
    __shared__ float tile[32][33];
    int bx = blockIdx.x * 32, by = blockIdx.y * 32;
    int tx = threadIdx.x & 31, ty = threadIdx.x >> 5;
#pragma unroll
    for (int i = 0; i < 4; i++)
        tile[ty + i * 8][tx] = __ldg(src + (size_t)(by + ty + i * 8) * 512 + bx + tx);
    __syncthreads();
#pragma unroll
    for (int i = 0; i < 4; i++)
        dst[(size_t)(bx + ty + i * 8) * 512 + by + tx] = tile[tx][ty + i * 8];
}

// ---------------- SIMT f32x2 gemm: C = A @ W^T (+bias), fp32 out; W row stride ldw ----------------
__global__ void __launch_bounds__(256)
gemm_nt(const float* __restrict__ A, const float* __restrict__ W,
        const float* __restrict__ bias, float* __restrict__ C,
        int M, int N, int K, int ldw)
{
    __shared__ __align__(16) float As[16][128];
    __shared__ __align__(16) float Ws[16][128];
    const int m0 = blockIdx.y * 128, n0 = blockIdx.x * 128;
    const int tid = threadIdx.x;
    const int tx = tid & 15, ty = tid >> 4;
    const int lrow = tid >> 1, lcol = (tid & 1) * 8;

    unsigned long long acc2[8][4];
#pragma unroll
    for (int i = 0; i < 8; i++)
#pragma unroll
        for (int jj = 0; jj < 4; jj++) acc2[i][jj] = 0ull;

    const float* Aload = A + (size_t)(m0 + lrow) * K + lcol;
    const float* Wload = W + (size_t)(n0 + lrow) * ldw + lcol;

    for (int k0 = 0; k0 < K; k0 += 16) {
        float4 a0 = __ldg((const float4*)(Aload + k0));
        float4 a1 = __ldg((const float4*)(Aload + k0 + 4));
        float4 w0 = __ldg((const float4*)(Wload + k0));
        float4 w1 = __ldg((const float4*)(Wload + k0 + 4));
        __syncthreads();
        As[lcol + 0][lrow] = a0.x; As[lcol + 1][lrow] = a0.y;
        As[lcol + 2][lrow] = a0.z; As[lcol + 3][lrow] = a0.w;
        As[lcol + 4][lrow] = a1.x; As[lcol + 5][lrow] = a1.y;
        As[lcol + 6][lrow] = a1.z; As[lcol + 7][lrow] = a1.w;
        Ws[lcol + 0][lrow] = w0.x; Ws[lcol + 1][lrow] = w0.y;
        Ws[lcol + 2][lrow] = w0.z; Ws[lcol + 3][lrow] = w0.w;
        Ws[lcol + 4][lrow] = w1.x; Ws[lcol + 5][lrow] = w1.y;
        Ws[lcol + 6][lrow] = w1.z; Ws[lcol + 7][lrow] = w1.w;
        __syncthreads();
#pragma unroll
        for (int kk = 0; kk < 16; kk++) {
            float4 av0 = *(const float4*)&As[kk][ty * 8];
            float4 av1 = *(const float4*)&As[kk][ty * 8 + 4];
            const ulonglong2* wp = (const ulonglong2*)&Ws[kk][tx * 8];
            ulonglong2 b01 = wp[0], b23 = wp[1];
            float a8[8] = {av0.x, av0.y, av0.z, av0.w, av1.x, av1.y, av1.z, av1.w};
#pragma unroll
            for (int i = 0; i < 8; i++) {
                unsigned long long a2 = pack2(a8[i]);
                ffma2(acc2[i][0], a2, b01.x);
                ffma2(acc2[i][1], a2, b01.y);
                ffma2(acc2[i][2], a2, b23.x);
                ffma2(acc2[i][3], a2, b23.y);
            }
        }
    }
#pragma unroll
    for (int i = 0; i < 8; i++) {
        float* Crow = C + (size_t)(m0 + ty * 8 + i) * N + n0 + tx * 8;
#pragma unroll
        for (int jj = 0; jj < 4; jj++) {
            float2 v = unpack2(acc2[i][jj]);
            if (bias) {
                v.x += __ldg(bias + n0 + tx * 8 + 2 * jj);
                v.y += __ldg(bias + n0 + tx * 8 + 2 * jj + 1);
            }
            *(float2*)(Crow + 2 * jj) = v;
        }
    }
}

// ---------------- SIMT f32x2 gemm (out_proj) -> bf16 hi/lo ----------------
__device__ __forceinline__ void split_bf16(float v, __nv_bfloat16& h, __nv_bfloat16& l)
{
    h = __float2bfloat16(v);
    l = __float2bfloat16(v - __bfloat162float(h));
}

__global__ void __launch_bounds__(256)
gemm_nt_split(const float* __restrict__ A, const float* __restrict__ W,
              const float* __restrict__ bias,
              __nv_bfloat16* __restrict__ Chi, __nv_bfloat16* __restrict__ Clo,
              int M, int N, int K)
{
    __shared__ __align__(16) float As[16][128];
    __shared__ __align__(16) float Ws[16][128];
    const int m0 = blockIdx.y * 128, n0 = blockIdx.x * 128;
    const int tid = threadIdx.x;
    const int tx = tid & 15, ty = tid >> 4;
    const int lrow = tid >> 1, lcol = (tid & 1) * 8;

    unsigned long long acc2[8][4];
#pragma unroll
    for (int i = 0; i < 8; i++)
#pragma unroll
        for (int jj = 0; jj < 4; jj++) acc2[i][jj] = 0ull;

    const float* Aload = A + (size_t)(m0 + lrow) * K + lcol;
    const float* Wload = W + (size_t)(n0 + lrow) * K + lcol;

    for (int k0 = 0; k0 < K; k0 += 16) {
        float4 a0 = __ldg((const float4*)(Aload + k0));
        float4 a1 = __ldg((const float4*)(Aload + k0 + 4));
        float4 w0 = __ldg((const float4*)(Wload + k0));
        float4 w1 = __ldg((const float4*)(Wload + k0 + 4));
        __syncthreads();
        As[lcol + 0][lrow] = a0.x; As[lcol + 1][lrow] = a0.y;
        As[lcol + 2][lrow] = a0.z; As[lcol + 3][lrow] = a0.w;
        As[lcol + 4][lrow] = a1.x; As[lcol + 5][lrow] = a1.y;
        As[lcol + 6][lrow] = a1.z; As[lcol + 7][lrow] = a1.w;
        Ws[lcol + 0][lrow] = w0.x; Ws[lcol + 1][lrow] = w0.y;
        Ws[lcol + 2][lrow] = w0.z; Ws[lcol + 3][lrow] = w0.w;
        Ws[lcol + 4][lrow] = w1.x; Ws[lcol + 5][lrow] = w1.y;
        Ws[lcol + 6][lrow] = w1.z; Ws[lcol + 7][lrow] = w1.w;
        __syncthreads();
#pragma unroll
        for (int kk = 0; kk < 16; kk++) {
            float4 av0 = *(const float4*)&As[kk][ty * 8];
            float4 av1 = *(const float4*)&As[kk][ty * 8 + 4];
            const ulonglong2* wp = (const ulonglong2*)&Ws[kk][tx * 8];
            ulonglong2 b01 = wp[0], b23 = wp[1];
            float a8[8] = {av0.x, av0.y, av0.z, av0.w, av1.x, av1.y, av1.z, av1.w};
#pragma unroll
            for (int i = 0; i < 8; i++) {
                unsigned long long a2 = pack2(a8[i]);
                ffma2(acc2[i][0], a2, b01.x);
                ffma2(acc2[i][1], a2, b01.y);
                ffma2(acc2[i][2], a2, b23.x);
                ffma2(acc2[i][3], a2, b23.y);
            }
        }
    }
#pragma unroll
    for (int i = 0; i < 8; i++) {
        size_t rowoff = (size_t)(m0 + ty * 8 + i) * N + n0 + tx * 8;
        unsigned short tmph[8], tmpl[8];
#pragma unroll
        for (int jj = 0; jj < 4; jj++) {
            float2 v = unpack2(acc2[i][jj]);
            v.x += __ldg(bias + n0 + tx * 8 + 2 * jj);
            v.y += __ldg(bias + n0 + tx * 8 + 2 * jj + 1);
            __nv_bfloat16 h0, l0, h1, l1;
            split_bf16(v.x, h0, l0);
            split_bf16(v.y, h1, l1);
            tmph[2 * jj] = __bfloat16_as_ushort(h0); tmph[2 * jj + 1] = __bfloat16_as_ushort(h1);
            tmpl[2 * jj] = __bfloat16_as_ushort(l0); tmpl[2 * jj + 1] = __bfloat16_as_ushort(l1);
        }
        uint2 H, L, H2, L2;
        H.x = (uint32_t)tmph[0] | ((uint32_t)tmph[1] << 16);
        H.y = (uint32_t)tmph[2] | ((uint32_t)tmph[3] << 16);
        L.x = (uint32_t)tmpl[0] | ((uint32_t)tmpl[1] << 16);
        L.y = (uint32_t)tmpl[2] | ((uint32_t)tmpl[3] << 16);
        H2.x = (uint32_t)tmph[4] | ((uint32_t)tmph[5] << 16);
        H2.y = (uint32_t)tmph[6] | ((uint32_t)tmph[7] << 16);
        L2.x = (uint32_t)tmpl[4] | ((uint32_t)tmpl[5] << 16);
        L2.y = (uint32_t)tmpl[6] | ((uint32_t)tmpl[7] << 16);
        *(uint2*)(Chi + rowoff) = H;  *(uint2*)(Chi + rowoff + 4) = H2;
        *(uint2*)(Clo + rowoff) = L;  *(uint2*)(Clo + rowoff + 4) = L2;
    }
}

// ---------------- fp32 -> bf16 hi/lo split (embed) ----------------
__global__ void __launch_bounds__(256)
conv_split(const float4* __restrict__ src, uint2* __restrict__ hi, uint2* __restrict__ lo)
{
    int i = blockIdx.x * 256 + threadIdx.x;
    float4 v = __ldg(src + i);
    __nv_bfloat16 h0, l0, h1, l1, h2, l2, h3, l3;
    split_bf16(v.x, h0, l0); split_bf16(v.y, h1, l1);
    split_bf16(v.z, h2, l2); split_bf16(v.w, h3, l3);
    uint2 H, L;
    H.x = (uint32_t)__bfloat16_as_ushort(h0) | ((uint32_t)__bfloat16_as_ushort(h1) << 16);
    H.y = (uint32_t)__bfloat16_as_ushort(h2) | ((uint32_t)__bfloat16_as_ushort(h3) << 16);
    L.x = (uint32_t)__bfloat16_as_ushort(l0) | ((uint32_t)__bfloat16_as_ushort(l1) << 16);
    L.y = (uint32_t)__bfloat16_as_ushort(l2) | ((uint32_t)__bfloat16_as_ushort(l3) << 16);
    hi[i] = H; lo[i] = L;
}

// ---------------- mma.sync bf16 3-pass GEMM: C = A @ B^T ----------------
static constexpr int KC = 32;
static constexpr int NCHUNK = En / KC;
static constexpr int ROWB = 80;
static constexpr int MATB = 128 * ROWB;
static constexpr int STAGEB = 4 * MATB;
static constexpr int GSMEM2 = 2 * STAGEB;

__device__ __forceinline__ void ldmA(uint32_t* r, uint32_t addr)
{
    asm volatile("ldmatrix.sync.aligned.m8n8.x4.shared.b16 {%0,%1,%2,%3}, [%4];"
                 : "=r"(r[0]), "=r"(r[1]), "=r"(r[2]), "=r"(r[3]) : "r"(addr));
}
__device__ __forceinline__ void ldmB(uint32_t* r, uint32_t addr)
{
    asm volatile("ldmatrix.sync.aligned.m8n8.x2.shared.b16 {%0,%1}, [%2];"
                 : "=r"(r[0]), "=r"(r[1]) : "r"(addr));
}
__device__ __forceinline__ void mma16816(float* d, const uint32_t* a, const uint32_t* b)
{
    asm volatile("mma.sync.aligned.m16n8k16.row.col.f32.bf16.bf16.f32 "
                 "{%0,%1,%2,%3}, {%4,%5,%6,%7}, {%8,%9}, {%0,%1,%2,%3};"
                 : "+f"(d[0]), "+f"(d[1]), "+f"(d[2]), "+f"(d[3])
                 : "r"(a[0]), "r"(a[1]), "r"(a[2]), "r"(a[3]), "r"(b[0]), "r"(b[1]));
}

__global__ void __launch_bounds__(256, 2)
gemm_bf16(const __nv_bfloat16* __restrict__ Ahi, const __nv_bfloat16* __restrict__ Alo,
          const __nv_bfloat16* __restrict__ Bhi, const __nv_bfloat16* __restrict__ Blo,
          float* __restrict__ C, int N, int K)
{
    extern __shared__ char smem[];
    const uint32_t su = s2u(smem);
    const int tid = threadIdx.x, wid = tid >> 5, lane = tid & 31;
    const int m0 = blockIdx.x * 128, n0 = blockIdx.y * 128;
    const int wm = wid & 1, wn = wid >> 1;

    const int ci0 = tid;
    auto load_stage = [&](int chunk) {
        const uint32_t sb = su + (chunk & 1) * STAGEB;
#pragma unroll
        for (int r8 = 0; r8 < 8; r8++) {
            int ci = ci0 + r8 * 256;
            int mat = ci >> 9, rem = ci & 511;
            int row = rem >> 2, seg = rem & 3;
            const __nv_bfloat16* g;
            if (mat == 0)      g = Ahi + (size_t)(m0 + row) * K + chunk * KC + seg * 8;
            else if (mat == 1) g = Alo + (size_t)(m0 + row) * K + chunk * KC + seg * 8;
            else if (mat == 2) g = Bhi + (size_t)(n0 + row) * K + chunk * KC + seg * 8;
            else               g = Blo + (size_t)(n0 + row) * K + chunk * KC + seg * 8;
            cp16(sb + mat * MATB + row * ROWB + seg * 16, g);
        }
        asm volatile("cp.async.commit_group;" ::: "memory");
    };

    float acc[4][4][4];
#pragma unroll
    for (int i = 0; i < 4; i++)
#pragma unroll
        for (int jj = 0; jj < 4; jj++)
#pragma unroll
            for (int k = 0; k < 4; k++) acc[i][jj][k] = 0.f;

    load_stage(0);
    load_stage(1);

    for (int c = 0; c < NCHUNK; c++) {
        if (c < NCHUNK - 1) asm volatile("cp.async.wait_group 1;" ::: "memory");
        else                asm volatile("cp.async.wait_group 0;" ::: "memory");
        __syncthreads();
        const uint32_t sb = su + (c & 1) * STAGEB;
        const uint32_t aHiB = sb,            aLoB = sb + MATB;
        const uint32_t bHiB = sb + 2 * MATB, bLoB = sb + 3 * MATB;
#pragma unroll
        for (int ks = 0; ks < 2; ks++) {
            const uint32_t aoff = (uint32_t)((wm * 64 + (lane & 15)) * ROWB
                                             + (ks * 16 + (lane >> 4) * 8) * 2);
            const int l = lane & 15;
            const uint32_t boff = (uint32_t)((wn * 32 + (l & 7)) * ROWB
                                             + (ks * 16 + (l >> 3) * 8) * 2);
            uint32_t ah[4][4], al[4][4], bh[4][2], bl[4][2];
#pragma unroll
            for (int mi = 0; mi < 4; mi++) {
                ldmA(ah[mi], aHiB + aoff + mi * 16 * ROWB);
                ldmA(al[mi], aLoB + aoff + mi * 16 * ROWB);
            }
#pragma unroll
            for (int ni = 0; ni < 4; ni++) {
                ldmB(bh[ni], bHiB + boff + ni * 8 * ROWB);
                ldmB(bl[ni], bLoB + boff + ni * 8 * ROWB);
            }
#pragma unroll
            for (int mi = 0; mi < 4; mi++)
#pragma unroll
                for (int ni = 0; ni < 4; ni++) {
                    mma16816(acc[mi][ni], ah[mi], bh[ni]);
                    mma16816(acc[mi][ni], ah[mi], bl[ni]);
                    mma16816(acc[mi][ni], al[mi], bh[ni]);
                }
        }
        __syncthreads();
        if (c + 2 < NCHUNK) load_stage(c + 2);
    }

    const int mbase = m0 + wm * 64 + (lane >> 2);
    const int nbase = n0 + wn * 32 + (lane & 3) * 2;
#pragma unroll
    for (int mi = 0; mi < 4; mi++)
#pragma unroll
        for (int ni = 0; ni < 4; ni++) {
            float* p0 = C + (size_t)(mbase + mi * 16) * N + nbase + ni * 8;
            float* p1 = C + (size_t)(mbase + mi * 16 + 8) * N + nbase + ni * 8;
            *(float2*)p0 = make_float2(acc[mi][ni][0], acc[mi][ni][1]);
            *(float2*)p1 = make_float2(acc[mi][ni][2], acc[mi][ni][3]);
        }
}

extern "C" void kernel_launch(void* const* d_in, const int* in_sizes, int n_in,
                              void* d_out, int out_size)
{
    const int*   tokens     = (const int*)d_in[0];
    const float* enc        = (const float*)d_in[1];
    const int*   mask       = (const int*)d_in[2];
    const float* embed      = (const float*)d_in[3];
    const float* w_ih0      = (const float*)d_in[4];
    const float* w_hh0      = (const float*)d_in[5];
    const float* b_ih0      = (const float*)d_in[6];
    const float* b_hh0      = (const float*)d_in[7];
    const float* w_ih1      = (const float*)d_in[8];
    const float* w_hh1      = (const float*)d_in[9];
    const float* b_ih1      = (const float*)d_in[10];
    const float* b_hh1      = (const float*)d_in[11];
    const float* attn_in_w  = (const float*)d_in[12];
    const float* attn_out_w = (const float*)d_in[13];
    const float* out_proj_w = (const float*)d_in[14];
    const float* out_proj_b = (const float*)d_in[15];
    float* out = (float*)d_out;

    float *dec, *encq, *attT, *xrow, *xw;
    __nv_bfloat16 *Ahi, *Alo, *Bhi, *Blo;
    cudaGetSymbolAddress((void**)&dec, g_dec);
    cudaGetSymbolAddress((void**)&encq, g_encq);
    cudaGetSymbolAddress((void**)&attT, g_attT);
    cudaGetSymbolAddress((void**)&xrow, g_x);
    cudaGetSymbolAddress((void**)&xw, g_xw);
    cudaGetSymbolAddress((void**)&Ahi, g_Ahi);
    cudaGetSymbolAddress((void**)&Alo, g_Alo);
    cudaGetSymbolAddress((void**)&Bhi, g_Bhi);
    cudaGetSymbolAddress((void**)&Blo, g_Blo);

    cudaFuncSetAttribute(gemm_bf16, cudaFuncAttributeMaxDynamicSharedMemorySize, GSMEM2);
    cudaFuncSetAttribute(recurrent_kernel, cudaFuncAttributeMaxDynamicSharedMemorySize, DSMEM);

    static cudaStream_t s2 = nullptr;
    static cudaEvent_t evA = nullptr, evB = nullptr;
    if (!s2) {
        cudaStreamCreateWithFlags(&s2, cudaStreamNonBlocking);
        cudaEventCreateWithFlags(&evA, cudaEventDisableTiming);
        cudaEventCreateWithFlags(&evB, cudaEventDisableTiming);
    }

    // side stream: embed hi/lo conversion (independent; overlaps pre-GEMMs + recurrence)
    cudaEventRecord(evA, 0);
    cudaStreamWaitEvent(s2, evA, 0);
    conv_split<<<Vn * En / 1024, 256, 0, s2>>>((const float4*)embed, (uint2*)Bhi, (uint2*)Blo);
    cudaEventRecord(evB, s2);

    // pre-GEMMs: encq = enc @ attn_in_w (phase C removal); xw = x @ w_ih0[:, :512]^T
    trans512<<<dim3(16, 16), 256>>>(attn_in_w, attT);
    gather_x<<<256, 256>>>(tokens, embed);
    gemm_nt<<<dim3(Hn / 128, (Bn * Sn) / 128), 256>>>(enc, attT, nullptr, encq,
                                                      Bn * Sn, Hn, Hn, Hn);
    gemm_nt<<<dim3(2048 / 128, (Bn * Tn) / 128), 256>>>(xrow, w_ih0, nullptr, xw,
                                                        Bn * Tn, 2048, 512, 1024);
    recurrent_kernel<<<NCTA, NTHR, DSMEM>>>(enc, mask,
                                            w_ih0, w_hh0, b_ih0, b_hh0,
                                            w_ih1, w_hh1, b_ih1, b_hh1,
                                            attn_out_w);
    gemm_nt_split<<<dim3(En / 128, (Bn * Tn) / 128), 256>>>(dec, out_proj_w, out_proj_b,
                                                            Ahi, Alo, Bn * Tn, En, Hn);
    cudaStreamWaitEvent(0, evB, 0);
    gemm_bf16<<<dim3((Bn * Tn) / 128, Vn / 128), 256, GSMEM2>>>(Ahi, Alo, Bhi, Blo, out, Vn, En);
}